// round 5
// baseline (speedup 1.0000x reference)
#include <cuda_runtime.h>
#include <cstddef>

#define BB 4
#define SS 2048
#define DDIM 1024
#define HH 16
#define DEPTH 64
#define MROWS (BB*SS)          // 8192
#define BH (BB*HH)             // 64

// Scratch (allocation-free rule: __device__ globals)
__device__ float g_q[(size_t)BB*HH*SS*DEPTH];       // 32 MB
__device__ float g_k[(size_t)BB*HH*SS*DEPTH];
__device__ float g_v[(size_t)BB*HH*SS*DEPTH];
__device__ float g_concat[(size_t)BB*SS*DDIM];      // 32 MB
__device__ float g_attn_scratch[(size_t)BB*HH*SS*SS]; // 1.07 GB fallback if attn not in d_out

// ---------------------------------------------------------------------------
// Projection GEMM: Y[8192,1024] = X[8192,1024] @ W[1024,1024] + bias
// 128x128 block tile, 16 k-tile, 256 threads, 8x8 register tile.
// HEAD_SPLIT: scatter output to [B,H,S,64] layout.
// ---------------------------------------------------------------------------
template<bool HEAD_SPLIT>
__global__ void __launch_bounds__(256) gemm1024_kernel(
    const float* __restrict__ X, const float* __restrict__ W,
    const float* __restrict__ bias, float* __restrict__ Y)
{
    const int K = DDIM, N = DDIM;
    __shared__ float As[16][132];   // transposed A tile [k][m]
    __shared__ float Bs[16][132];   // B tile [k][n]

    const int m0 = blockIdx.y * 128;
    const int n0 = blockIdx.x * 128;
    const int tid = threadIdx.x;
    const int tx = tid & 15;        // n direction
    const int ty = tid >> 4;        // m direction

    float acc[8][8];
    #pragma unroll
    for (int i = 0; i < 8; i++)
        #pragma unroll
        for (int j = 0; j < 8; j++) acc[i][j] = 0.f;

    for (int kt = 0; kt < K; kt += 16) {
        #pragma unroll
        for (int it = 0; it < 8; it++) {
            int e = it * 256 + tid;
            int row = e >> 4, col = e & 15;                  // A: 128 x 16
            As[col][row] = X[(size_t)(m0 + row) * K + kt + col];
        }
        #pragma unroll
        for (int it = 0; it < 8; it++) {
            int e = it * 256 + tid;
            int row = e >> 7, col = e & 127;                 // B: 16 x 128
            Bs[row][col] = W[(size_t)(kt + row) * N + n0 + col];
        }
        __syncthreads();

        #pragma unroll
        for (int kk = 0; kk < 16; kk++) {
            float a[8], b[8];
            #pragma unroll
            for (int i = 0; i < 8; i++) a[i] = As[kk][ty * 8 + i];
            #pragma unroll
            for (int j = 0; j < 8; j++) b[j] = Bs[kk][tx * 8 + j];
            #pragma unroll
            for (int i = 0; i < 8; i++)
                #pragma unroll
                for (int j = 0; j < 8; j++)
                    acc[i][j] += a[i] * b[j];
        }
        __syncthreads();
    }

    #pragma unroll
    for (int i = 0; i < 8; i++) {
        int m = m0 + ty * 8 + i;
        int bi = m / SS, s = m % SS;
        #pragma unroll
        for (int j = 0; j < 8; j++) {
            int n = n0 + tx * 8 + j;
            float v = acc[i][j] + bias[n];
            if (HEAD_SPLIT) {
                int h = n >> 6, d = n & 63;
                g_dummy_noop:;
                Y[(((size_t)(bi * HH + h)) * SS + s) * DEPTH + d] = v;
            } else {
                Y[(size_t)m * N + n] = v;
            }
        }
    }
}

// ---------------------------------------------------------------------------
// Scores: per (b,h), 64x64 tile of q @ k^T * scale + mask * (-1e9)
// grid: (S/64, S/64, B*H), 256 threads, 4x4 register tile, K=64 fully resident.
// ---------------------------------------------------------------------------
__global__ void __launch_bounds__(256) scores_kernel(
    const float* __restrict__ mask, float* __restrict__ attn)
{
    const int bh = blockIdx.z;
    const int q0 = blockIdx.y * 64;
    const int k0 = blockIdx.x * 64;
    const int b = bh >> 4;   // / H

    __shared__ float qs[64][65];  // [d][qrow]
    __shared__ float ks[64][65];  // [d][krow]

    const float* qbase = g_q + (size_t)bh * SS * DEPTH;
    const float* kbase = g_k + (size_t)bh * SS * DEPTH;
    const int tid = threadIdx.x;

    #pragma unroll
    for (int it = 0; it < 16; it++) {
        int e = it * 256 + tid;
        int row = e >> 6, d = e & 63;
        qs[d][row] = qbase[(size_t)(q0 + row) * DEPTH + d];
        ks[d][row] = kbase[(size_t)(k0 + row) * DEPTH + d];
    }
    __syncthreads();

    const int tx = tid & 15;   // key direction
    const int ty = tid >> 4;   // query direction
    float acc[4][4];
    #pragma unroll
    for (int i = 0; i < 4; i++)
        #pragma unroll
        for (int j = 0; j < 4; j++) acc[i][j] = 0.f;

    #pragma unroll 8
    for (int d = 0; d < 64; d++) {
        float a[4], c[4];
        #pragma unroll
        for (int i = 0; i < 4; i++) a[i] = qs[d][ty * 4 + i];
        #pragma unroll
        for (int j = 0; j < 4; j++) c[j] = ks[d][tx * 4 + j];
        #pragma unroll
        for (int i = 0; i < 4; i++)
            #pragma unroll
            for (int j = 0; j < 4; j++)
                acc[i][j] += a[i] * c[j];
    }

    const float scale = 0.125f;  // 1/sqrt(64)
    #pragma unroll
    for (int i = 0; i < 4; i++) {
        int qg = q0 + ty * 4 + i;
        #pragma unroll
        for (int j = 0; j < 4; j++) {
            int kg = k0 + tx * 4 + j;
            float mv = mask[((size_t)b * SS + qg) * SS + kg];
            attn[(((size_t)bh) * SS + qg) * SS + kg] = acc[i][j] * scale + mv * (-1e9f);
        }
    }
}

// ---------------------------------------------------------------------------
// Row softmax in place. One block per row, 8 elements/thread held in registers.
// ---------------------------------------------------------------------------
__global__ void __launch_bounds__(256) softmax_kernel(float* __restrict__ attn)
{
    float* p = attn + (size_t)blockIdx.x * SS;
    const int tid = threadIdx.x;

    float v[8];
    float mx = -3.4e38f;
    #pragma unroll
    for (int i = 0; i < 8; i++) {
        v[i] = p[i * 256 + tid];
        mx = fmaxf(mx, v[i]);
    }
    #pragma unroll
    for (int o = 16; o > 0; o >>= 1)
        mx = fmaxf(mx, __shfl_xor_sync(0xffffffffu, mx, o));

    __shared__ float red[8];
    if ((tid & 31) == 0) red[tid >> 5] = mx;
    __syncthreads();
    float m = red[0];
    #pragma unroll
    for (int i = 1; i < 8; i++) m = fmaxf(m, red[i]);
    __syncthreads();

    float s = 0.f;
    #pragma unroll
    for (int i = 0; i < 8; i++) {
        v[i] = __expf(v[i] - m);
        s += v[i];
    }
    #pragma unroll
    for (int o = 16; o > 0; o >>= 1)
        s += __shfl_xor_sync(0xffffffffu, s, o);
    if ((tid & 31) == 0) red[tid >> 5] = s;
    __syncthreads();
    float tot = 0.f;
    #pragma unroll
    for (int i = 0; i < 8; i++) tot += red[i];

    float inv = 1.0f / tot;
    #pragma unroll
    for (int i = 0; i < 8; i++)
        p[i * 256 + tid] = v[i] * inv;
}

// ---------------------------------------------------------------------------
// AV: rep[b,h] = attn[b,h](2048x2048) @ v[b,h](2048x64) -> concat layout
// grid: (S/64, B*H), 256 threads, 64x64 output tile, 4x4 register tile.
// ---------------------------------------------------------------------------
__global__ void __launch_bounds__(256) av_kernel(const float* __restrict__ attn)
{
    const int bh = blockIdx.y;
    const int m0 = blockIdx.x * 64;
    const int b = bh >> 4, h = bh & 15;

    __shared__ float As[64][65];  // [qrow][k]
    __shared__ float Vs[64][65];  // [k][d]

    const float* abase = attn + (size_t)bh * SS * SS;
    const float* vbase = g_v + (size_t)bh * SS * DEPTH;
    const int tid = threadIdx.x;
    const int tx = tid & 15;   // d direction
    const int ty = tid >> 4;   // q direction

    float acc[4][4];
    #pragma unroll
    for (int i = 0; i < 4; i++)
        #pragma unroll
        for (int j = 0; j < 4; j++) acc[i][j] = 0.f;

    for (int kt = 0; kt < SS; kt += 64) {
        #pragma unroll
        for (int it = 0; it < 16; it++) {
            int e = it * 256 + tid;
            int row = e >> 6, c = e & 63;
            As[row][c] = abase[(size_t)(m0 + row) * SS + kt + c];
            Vs[row][c] = vbase[(size_t)(kt + row) * DEPTH + c];
        }
        __syncthreads();

        #pragma unroll 16
        for (int kk = 0; kk < 64; kk++) {
            float a[4], c[4];
            #pragma unroll
            for (int i = 0; i < 4; i++) a[i] = As[ty * 4 + i][kk];
            #pragma unroll
            for (int j = 0; j < 4; j++) c[j] = Vs[kk][tx * 4 + j];
            #pragma unroll
            for (int i = 0; i < 4; i++)
                #pragma unroll
                for (int j = 0; j < 4; j++)
                    acc[i][j] += a[i] * c[j];
        }
        __syncthreads();
    }

    #pragma unroll
    for (int i = 0; i < 4; i++) {
        int s = m0 + ty * 4 + i;
        #pragma unroll
        for (int j = 0; j < 4; j++) {
            int d = tx * 4 + j;
            g_concat[((size_t)b * SS + s) * DDIM + h * DEPTH + d] = acc[i][j];
        }
    }
}

// ---------------------------------------------------------------------------
extern "C" void kernel_launch(void* const* d_in, const int* in_sizes, int n_in,
                              void* d_out, int out_size)
{
    const float* Q    = (const float*)d_in[0];
    const float* K    = (const float*)d_in[1];
    const float* V    = (const float*)d_in[2];
    const float* Mask = (const float*)d_in[3];
    const float* Wq   = (const float*)d_in[4];
    const float* bq   = (const float*)d_in[5];
    const float* Wk   = (const float*)d_in[6];
    const float* bk   = (const float*)d_in[7];
    const float* Wv   = (const float*)d_in[8];
    const float* bv   = (const float*)d_in[9];
    const float* Wo   = (const float*)d_in[10];
    const float* bo   = (const float*)d_in[11];

    float* out = (float*)d_out;

    const size_t out_elems  = (size_t)BB * SS * DDIM;       //   8,388,608
    const size_t attn_elems = (size_t)BB * HH * SS * SS;    // 268,435,456

    float *qp, *kp, *vp, *cp, *attn;
    cudaGetSymbolAddress((void**)&qp, g_q);
    cudaGetSymbolAddress((void**)&kp, g_k);
    cudaGetSymbolAddress((void**)&vp, g_v);
    cudaGetSymbolAddress((void**)&cp, g_concat);

    // If the harness output carries (out, attn), write attn straight into d_out.
    if ((size_t)out_size >= out_elems + attn_elems) {
        attn = out + out_elems;
    } else {
        cudaGetSymbolAddress((void**)&attn, g_attn_scratch);
    }

    dim3 gGemm(DDIM / 128, MROWS / 128);   // (8, 64)
    gemm1024_kernel<true><<<gGemm, 256>>>(Q, Wq, bq, qp);
    gemm1024_kernel<true><<<gGemm, 256>>>(K, Wk, bk, kp);
    gemm1024_kernel<true><<<gGemm, 256>>>(V, Wv, bv, vp);

    dim3 gScores(SS / 64, SS / 64, BH);    // (32, 32, 64)
    scores_kernel<<<gScores, 256>>>(Mask, attn);

    softmax_kernel<<<(unsigned)(BH * SS), 256>>>(attn);   // 131072 rows

    dim3 gAV(SS / 64, BH);                 // (32, 64)
    av_kernel<<<gAV, 256>>>(attn);

    gemm1024_kernel<false><<<gGemm, 256>>>(cp, Wo, bo, out);
}

// round 7
// speedup vs baseline: 1.3562x; 1.3562x over previous
#include <cuda_runtime.h>
#include <cstddef>

#define BB 4
#define SS 2048
#define DDIM 1024
#define HH 16
#define DEPTH 64
#define MROWS (BB*SS)          // 8192
#define BH (BB*HH)             // 64

typedef unsigned long long u64;

// Scratch (allocation-free rule: __device__ globals)
__device__ float g_q[(size_t)BB*HH*SS*DEPTH];       // 32 MB
__device__ float g_k[(size_t)BB*HH*SS*DEPTH];
__device__ float g_v[(size_t)BB*HH*SS*DEPTH];
__device__ float g_concat[(size_t)BB*SS*DDIM];      // 32 MB
__device__ float g_attn_scratch[(size_t)BB*HH*SS*SS]; // 1.07 GB fallback if attn not in d_out

// ---------------------------------------------------------------------------
// Packed fp32x2 helpers (FFMA2 path — only reachable via PTX fma.rn.f32x2)
// ---------------------------------------------------------------------------
__device__ __forceinline__ u64 pk2(float lo, float hi) {
    u64 r; asm("mov.b64 %0, {%1, %2};" : "=l"(r) : "f"(lo), "f"(hi)); return r;
}
__device__ __forceinline__ void up2(float& lo, float& hi, u64 v) {
    asm("mov.b64 {%0, %1}, %2;" : "=f"(lo), "=f"(hi) : "l"(v));
}
__device__ __forceinline__ void fma2(u64& d, u64 a, u64 b) {
    asm("fma.rn.f32x2 %0, %1, %2, %0;" : "+l"(d) : "l"(a), "l"(b));
}

// ---------------------------------------------------------------------------
// Projection GEMM: Y[8192,1024] = X[8192,1024] @ W[1024,1024] + bias
// 128x128 block tile, 16 k-tile, 256 threads.
// Per thread: 8 rows (blocked ty*8+i) x 8 cols (pairs at n0 + 2*tx + 32*j).
// Accumulators packed over the column pair (FFMA2).
// HEAD_SPLIT: scatter output to [B,H,S,64] layout.
// ---------------------------------------------------------------------------
template<bool HEAD_SPLIT>
__global__ void __launch_bounds__(256) gemm1024_kernel(
    const float* __restrict__ X, const float* __restrict__ W,
    const float* __restrict__ bias, float* __restrict__ Y)
{
    const int K = DDIM, N = DDIM;
    __shared__ float As[16][132];   // transposed A tile [k][m]
    __shared__ float Bs[16][132];   // B tile [k][n]

    const int m0 = blockIdx.y * 128;
    const int n0 = blockIdx.x * 128;
    const int tid = threadIdx.x;
    const int tx = tid & 15;        // n direction
    const int ty = tid >> 4;        // m direction

    u64 acc[8][4];
    #pragma unroll
    for (int i = 0; i < 8; i++)
        #pragma unroll
        for (int j = 0; j < 4; j++) acc[i][j] = 0ull;

    for (int kt = 0; kt < K; kt += 16) {
        // A tile fill: 128x16, transposed into As[k][m]. float4 gmem loads.
        #pragma unroll
        for (int it = 0; it < 2; it++) {
            int f = it * 256 + tid;          // 512 float4s
            int row = f >> 2, c4 = f & 3;
            float4 v = *(const float4*)&X[(size_t)(m0 + row) * K + kt + c4 * 4];
            As[c4 * 4 + 0][row] = v.x;
            As[c4 * 4 + 1][row] = v.y;
            As[c4 * 4 + 2][row] = v.z;
            As[c4 * 4 + 3][row] = v.w;
        }
        // B tile fill: 16x128, natural layout, float4 stores.
        #pragma unroll
        for (int it = 0; it < 2; it++) {
            int f = it * 256 + tid;          // 512 float4s
            int row = f >> 5, c4 = f & 31;
            float4 v = *(const float4*)&W[(size_t)(kt + row) * N + n0 + c4 * 4];
            *(float4*)&Bs[row][c4 * 4] = v;
        }
        __syncthreads();

        #pragma unroll
        for (int kk = 0; kk < 16; kk++) {
            float4 a0 = *(const float4*)&As[kk][ty * 8];
            float4 a1 = *(const float4*)&As[kk][ty * 8 + 4];
            u64 ad[8];
            ad[0] = pk2(a0.x, a0.x); ad[1] = pk2(a0.y, a0.y);
            ad[2] = pk2(a0.z, a0.z); ad[3] = pk2(a0.w, a0.w);
            ad[4] = pk2(a1.x, a1.x); ad[5] = pk2(a1.y, a1.y);
            ad[6] = pk2(a1.z, a1.z); ad[7] = pk2(a1.w, a1.w);
            u64 b[4];
            #pragma unroll
            for (int j = 0; j < 4; j++)
                b[j] = *(const u64*)&Bs[kk][2 * tx + 32 * j];
            #pragma unroll
            for (int i = 0; i < 8; i++)
                #pragma unroll
                for (int j = 0; j < 4; j++)
                    fma2(acc[i][j], ad[i], b[j]);
        }
        __syncthreads();
    }

    #pragma unroll
    for (int i = 0; i < 8; i++) {
        int m = m0 + ty * 8 + i;
        int bi = m >> 11, s = m & (SS - 1);
        #pragma unroll
        for (int j = 0; j < 4; j++) {
            int n = n0 + 2 * tx + 32 * j;
            float lo, hi;
            up2(lo, hi, acc[i][j]);
            lo += bias[n];
            hi += bias[n + 1];
            if (HEAD_SPLIT) {
                int h = n >> 6, d = n & 63;   // n even -> d, d+1 same head
                *(float2*)&Y[(((size_t)(bi * HH + h)) * SS + s) * DEPTH + d] =
                    make_float2(lo, hi);
            } else {
                *(float2*)&Y[(size_t)m * N + n] = make_float2(lo, hi);
            }
        }
    }
}

// ---------------------------------------------------------------------------
// Scores: per (b,h), 128q x 64k tile of q @ k^T * scale + mask * (-1e9)
// Dot-product form: accumulators packed over the d-reduction (FFMA2),
// horizontal add at the end. Per thread 8q x 4k, strided ownership
// (rows ty+16i, cols tx+16j). ks uses an 8B XOR swizzle -> conflict-free.
// grid: (BH, S/64, S/128) — x=bh so all heads of a batch share mask in L2.
// ---------------------------------------------------------------------------
__global__ void __launch_bounds__(256) scores_kernel(
    const float* __restrict__ mask, float* __restrict__ attn)
{
    __shared__ float qs[128 * 64];   // [qrow][d], no pad (reads are broadcast)
    __shared__ float ks[64 * 64];    // [krow][d ^ 2*(krow&15)] swizzled

    const int bh = blockIdx.x;
    const int k0 = blockIdx.y * 64;
    const int q0 = blockIdx.z * 128;
    const int b = bh >> 4;

    const float* qbase = g_q + (size_t)bh * SS * DEPTH;
    const float* kbase = g_k + (size_t)bh * SS * DEPTH;
    const int tid = threadIdx.x;

    // Fill qs: 128x64 floats = 2048 float4
    #pragma unroll
    for (int it = 0; it < 8; it++) {
        int f = it * 256 + tid;
        int row = f >> 4, d4 = f & 15;
        float4 v = *(const float4*)&qbase[(size_t)(q0 + row) * DEPTH + d4 * 4];
        *(float4*)&qs[row * 64 + d4 * 4] = v;
    }
    // Fill ks with swizzle: element (row,d) stored at col d ^ (2*(row&15))
    #pragma unroll
    for (int it = 0; it < 4; it++) {
        int f = it * 256 + tid;
        int row = f >> 4, d4 = f & 15;
        float4 v = *(const float4*)&kbase[(size_t)(k0 + row) * DEPTH + d4 * 4];
        int s = 2 * (row & 15);
        int d0 = d4 * 4;
        *(float2*)&ks[row * 64 + (d0 ^ s)]       = make_float2(v.x, v.y);
        *(float2*)&ks[row * 64 + ((d0 + 2) ^ s)] = make_float2(v.z, v.w);
    }
    __syncthreads();

    const int tx = tid & 15;   // key direction (cols tx+16j)
    const int ty = tid >> 4;   // query direction (rows ty+16i)
    const int swz = 2 * tx;    // (tx+16j)&15 == tx for all j

    u64 acc[8][4];
    #pragma unroll
    for (int i = 0; i < 8; i++)
        #pragma unroll
        for (int j = 0; j < 4; j++) acc[i][j] = 0ull;

    #pragma unroll 8
    for (int d2 = 0; d2 < 32; d2++) {
        int d = d2 * 2;
        u64 q2[8], k2[4];
        #pragma unroll
        for (int i = 0; i < 8; i++)
            q2[i] = *(const u64*)&qs[(ty + 16 * i) * 64 + d];
        #pragma unroll
        for (int j = 0; j < 4; j++)
            k2[j] = *(const u64*)&ks[(tx + 16 * j) * 64 + (d ^ swz)];
        #pragma unroll
        for (int i = 0; i < 8; i++)
            #pragma unroll
            for (int j = 0; j < 4; j++)
                fma2(acc[i][j], q2[i], k2[j]);
    }

    const float scale = 0.125f;  // 1/sqrt(64)
    #pragma unroll
    for (int i = 0; i < 8; i++) {
        int qg = q0 + ty + 16 * i;
        #pragma unroll
        for (int j = 0; j < 4; j++) {
            int kg = k0 + tx + 16 * j;
            float lo, hi;
            up2(lo, hi, acc[i][j]);
            float mv = mask[((size_t)b * SS + qg) * SS + kg];
            attn[(((size_t)bh) * SS + qg) * SS + kg] =
                (lo + hi) * scale + mv * (-1e9f);
        }
    }
}

// ---------------------------------------------------------------------------
// Row softmax in place. One block per row, 8 elements/thread in registers.
// ---------------------------------------------------------------------------
__global__ void __launch_bounds__(256) softmax_kernel(float* __restrict__ attn)
{
    float* p = attn + (size_t)blockIdx.x * SS;
    const int tid = threadIdx.x;

    float v[8];
    float mx = -3.4e38f;
    #pragma unroll
    for (int i = 0; i < 8; i++) {
        v[i] = p[i * 256 + tid];
        mx = fmaxf(mx, v[i]);
    }
    #pragma unroll
    for (int o = 16; o > 0; o >>= 1)
        mx = fmaxf(mx, __shfl_xor_sync(0xffffffffu, mx, o));

    __shared__ float red[8];
    if ((tid & 31) == 0) red[tid >> 5] = mx;
    __syncthreads();
    float m = red[0];
    #pragma unroll
    for (int i = 1; i < 8; i++) m = fmaxf(m, red[i]);
    __syncthreads();

    float s = 0.f;
    #pragma unroll
    for (int i = 0; i < 8; i++) {
        v[i] = __expf(v[i] - m);
        s += v[i];
    }
    #pragma unroll
    for (int o = 16; o > 0; o >>= 1)
        s += __shfl_xor_sync(0xffffffffu, s, o);
    if ((tid & 31) == 0) red[tid >> 5] = s;
    __syncthreads();
    float tot = 0.f;
    #pragma unroll
    for (int i = 0; i < 8; i++) tot += red[i];

    float inv = 1.0f / tot;
    #pragma unroll
    for (int i = 0; i < 8; i++)
        p[i * 256 + tid] = v[i] * inv;
}

// ---------------------------------------------------------------------------
// AV: rep[b,h] = attn[b,h](2048x2048) @ v[b,h](2048x64) -> concat layout
// Dot-product form over k (FFMA2 packed over k-pairs). V held TRANSPOSED in
// smem (Vs_t[dv][k]) with 8B XOR swizzle -> conflict-free reads.
// Block tile 128q x 64dv, per thread 8x4 strided. grid: (BH, S/128).
// ---------------------------------------------------------------------------
__global__ void __launch_bounds__(256) av_kernel(const float* __restrict__ attn)
{
    __shared__ float As[128 * 64];   // [qrow][k], reads broadcast
    __shared__ float Vs[64 * 64];    // [dv][k ^ 2*(dv&15)] swizzled

    const int bh = blockIdx.x;
    const int m0 = blockIdx.y * 128;
    const int b = bh >> 4, h = bh & 15;

    const float* abase = attn + (size_t)bh * SS * SS;
    const float* vbase = g_v + (size_t)bh * SS * DEPTH;
    const int tid = threadIdx.x;
    const int tx = tid & 15;   // dv direction (cols tx+16j)
    const int ty = tid >> 4;   // q direction (rows ty+16i)
    const int swz = 2 * tx;

    u64 acc[8][4];
    #pragma unroll
    for (int i = 0; i < 8; i++)
        #pragma unroll
        for (int j = 0; j < 4; j++) acc[i][j] = 0ull;

    for (int kt = 0; kt < SS; kt += 64) {
        // attn tile 128x64: 2048 float4
        #pragma unroll
        for (int it = 0; it < 8; it++) {
            int f = it * 256 + tid;
            int row = f >> 4, c4 = f & 15;
            float4 v = *(const float4*)&abase[(size_t)(m0 + row) * SS + kt + c4 * 4];
            *(float4*)&As[row * 64 + c4 * 4] = v;
        }
        // V tile 64x64 transposed into Vs[dv][k^swz]
        #pragma unroll
        for (int it = 0; it < 4; it++) {
            int f = it * 256 + tid;
            int k = f >> 4, d4 = f & 15;
            float4 v = *(const float4*)&vbase[(size_t)(kt + k) * DEPTH + d4 * 4];
            float c[4] = {v.x, v.y, v.z, v.w};
            #pragma unroll
            for (int cc = 0; cc < 4; cc++) {
                int dv = d4 * 4 + cc;
                Vs[dv * 64 + (k ^ (2 * (dv & 15)))] = c[cc];
            }
        }
        __syncthreads();

        #pragma unroll 8
        for (int k2i = 0; k2i < 32; k2i++) {
            int k = k2i * 2;
            u64 a2[8], v2[4];
            #pragma unroll
            for (int i = 0; i < 8; i++)
                a2[i] = *(const u64*)&As[(ty + 16 * i) * 64 + k];
            #pragma unroll
            for (int j = 0; j < 4; j++)
                v2[j] = *(const u64*)&Vs[(tx + 16 * j) * 64 + (k ^ swz)];
            #pragma unroll
            for (int i = 0; i < 8; i++)
                #pragma unroll
                for (int j = 0; j < 4; j++)
                    fma2(acc[i][j], a2[i], v2[j]);
        }
        __syncthreads();
    }

    #pragma unroll
    for (int i = 0; i < 8; i++) {
        int s = m0 + ty + 16 * i;
        #pragma unroll
        for (int j = 0; j < 4; j++) {
            int dv = tx + 16 * j;
            float lo, hi;
            up2(lo, hi, acc[i][j]);
            g_concat[((size_t)b * SS + s) * DDIM + h * DEPTH + dv] = lo + hi;
        }
    }
}

// ---------------------------------------------------------------------------
extern "C" void kernel_launch(void* const* d_in, const int* in_sizes, int n_in,
                              void* d_out, int out_size)
{
    const float* Q    = (const float*)d_in[0];
    const float* K    = (const float*)d_in[1];
    const float* V    = (const float*)d_in[2];
    const float* Mask = (const float*)d_in[3];
    const float* Wq   = (const float*)d_in[4];
    const float* bq   = (const float*)d_in[5];
    const float* Wk   = (const float*)d_in[6];
    const float* bk   = (const float*)d_in[7];
    const float* Wv   = (const float*)d_in[8];
    const float* bv   = (const float*)d_in[9];
    const float* Wo   = (const float*)d_in[10];
    const float* bo   = (const float*)d_in[11];

    float* out = (float*)d_out;

    const size_t out_elems  = (size_t)BB * SS * DDIM;       //   8,388,608
    const size_t attn_elems = (size_t)BB * HH * SS * SS;    // 268,435,456

    float *qp, *kp, *vp, *cp, *attn;
    cudaGetSymbolAddress((void**)&qp, g_q);
    cudaGetSymbolAddress((void**)&kp, g_k);
    cudaGetSymbolAddress((void**)&vp, g_v);
    cudaGetSymbolAddress((void**)&cp, g_concat);

    // If the harness output carries (out, attn), write attn straight into d_out.
    if ((size_t)out_size >= out_elems + attn_elems) {
        attn = out + out_elems;
    } else {
        cudaGetSymbolAddress((void**)&attn, g_attn_scratch);
    }

    dim3 gGemm(DDIM / 128, MROWS / 128);   // (8, 64)
    gemm1024_kernel<true><<<gGemm, 256>>>(Q, Wq, bq, qp);
    gemm1024_kernel<true><<<gGemm, 256>>>(K, Wk, bk, kp);
    gemm1024_kernel<true><<<gGemm, 256>>>(V, Wv, bv, vp);

    dim3 gScores(BH, SS / 64, SS / 128);   // (64, 32, 16) — x=bh for mask L2 reuse
    scores_kernel<<<gScores, 256>>>(Mask, attn);

    softmax_kernel<<<(unsigned)(BH * SS), 256>>>(attn);   // 131072 rows

    dim3 gAV(BH, SS / 128);                // (64, 16)
    av_kernel<<<gAV, 256>>>(attn);

    gemm1024_kernel<false><<<gGemm, 256>>>(cp, Wo, bo, out);
}

// round 11
// speedup vs baseline: 1.9728x; 1.4546x over previous
#include <cuda_runtime.h>
#include <cstddef>
#include <cstdint>

#define BB 4
#define SS 2048
#define DDIM 1024
#define HH 16
#define DEPTH 64
#define MROWS (BB*SS)          // 8192
#define BH (BB*HH)             // 64

// Scratch (allocation-free rule: __device__ globals)
__device__ float g_q[(size_t)BB*HH*SS*DEPTH];       // 32 MB
__device__ float g_k[(size_t)BB*HH*SS*DEPTH];
__device__ float g_v[(size_t)BB*HH*SS*DEPTH];
__device__ float g_concat[(size_t)BB*SS*DDIM];      // 32 MB
__device__ float g_attn_scratch[(size_t)BB*HH*SS*SS]; // 1.07 GB fallback

// ---------------------------------------------------------------------------
// tf32 helpers
// ---------------------------------------------------------------------------
__device__ __forceinline__ float to_tf32(float x) {
    float r; asm("cvt.rna.tf32.f32 %0, %1;" : "=f"(r) : "f"(x)); return r;
}
__device__ __forceinline__ float4 cvt4(float4 v) {
    float4 t;
    t.x = to_tf32(v.x); t.y = to_tf32(v.y);
    t.z = to_tf32(v.z); t.w = to_tf32(v.w);
    return t;
}
// D += A(16x8,row) * B(8x8,col) ; tf32 inputs, fp32 accum
__device__ __forceinline__ void mma_tf32(float* d, const uint32_t* a, const uint32_t* b) {
    asm volatile(
        "mma.sync.aligned.m16n8k8.row.col.f32.tf32.tf32.f32 "
        "{%0,%1,%2,%3}, {%4,%5,%6,%7}, {%8,%9}, {%0,%1,%2,%3};"
        : "+f"(d[0]), "+f"(d[1]), "+f"(d[2]), "+f"(d[3])
        : "r"(a[0]), "r"(a[1]), "r"(a[2]), "r"(a[3]), "r"(b[0]), "r"(b[1]));
}
__device__ __forceinline__ uint32_t fau(float x) { return __float_as_uint(x); }

// Fragment lane decomposition (identical for all kernels):
//   g = lane>>2 (groupID), tg = lane&3
// A frag (m16 k8, row-major over m): a0=(g,tg) a1=(g+8,tg) a2=(g,tg+4) a3=(g+8,tg+4)
// B frag (k8 n8, col-major): b0=(k=tg,n=g) b1=(k=tg+4,n=g)
// D frag: c0=(g,2tg) c1=(g,2tg+1) c2=(g+8,2tg) c3=(g+8,2tg+1)
//
// Conflict-free smem rules used below:
//   [row-major over non-reduction dim], stride ≡ 4 (mod 32): bank = 4g+tg  (distinct)
//   [k-major], stride ≡ 8 (mod 32):                          bank = 8tg+g  (distinct)

// ---------------------------------------------------------------------------
// Projection/output GEMM: Y[8192,1024] = X @ W + bias
// Block 128x128, ktile 32, 8 warps (2m x 4n), warp tile 64x32.
// ---------------------------------------------------------------------------
template<bool HEAD_SPLIT>
__global__ void __launch_bounds__(256) gemm_tc(
    const float* __restrict__ X, const float* __restrict__ W,
    const float* __restrict__ bias, float* __restrict__ Y)
{
    __shared__ float As[128][36];    // [m][k] stride 36 ≡ 4 (mod 32)
    __shared__ float Bs[32][136];    // [k][n] stride 136 ≡ 8 (mod 32)

    const int m0 = blockIdx.y * 128;
    const int n0 = blockIdx.x * 128;
    const int tid = threadIdx.x;
    const int w = tid >> 5, lane = tid & 31;
    const int wm = w >> 2, wn = w & 3;      // 2 x 4 warp grid
    const int g = lane >> 2, tg = lane & 3;

    float acc[4][4][4];
    #pragma unroll
    for (int mt = 0; mt < 4; mt++)
        #pragma unroll
        for (int nt = 0; nt < 4; nt++)
            #pragma unroll
            for (int r = 0; r < 4; r++) acc[mt][nt][r] = 0.f;

    for (int kt = 0; kt < DDIM; kt += 32) {
        #pragma unroll
        for (int it = 0; it < 4; it++) {              // A: 128x32 = 1024 float4
            int f = it * 256 + tid;
            int row = f >> 3, c4 = f & 7;
            float4 v = *(const float4*)&X[(size_t)(m0 + row) * DDIM + kt + c4 * 4];
            *(float4*)&As[row][c4 * 4] = cvt4(v);
        }
        #pragma unroll
        for (int it = 0; it < 4; it++) {              // B: 32x128 = 1024 float4
            int f = it * 256 + tid;
            int row = f >> 5, c4 = f & 31;
            float4 v = *(const float4*)&W[(size_t)(kt + row) * DDIM + n0 + c4 * 4];
            *(float4*)&Bs[row][c4 * 4] = cvt4(v);
        }
        __syncthreads();

        #pragma unroll
        for (int ks = 0; ks < 4; ks++) {
            int kc = ks * 8;
            uint32_t a[4][4], b[4][2];
            #pragma unroll
            for (int mt = 0; mt < 4; mt++) {
                int rm = wm * 64 + mt * 16;
                a[mt][0] = fau(As[rm + g][kc + tg]);
                a[mt][1] = fau(As[rm + g + 8][kc + tg]);
                a[mt][2] = fau(As[rm + g][kc + tg + 4]);
                a[mt][3] = fau(As[rm + g + 8][kc + tg + 4]);
            }
            #pragma unroll
            for (int nt = 0; nt < 4; nt++) {
                int cn = wn * 32 + nt * 8 + g;
                b[nt][0] = fau(Bs[kc + tg][cn]);
                b[nt][1] = fau(Bs[kc + tg + 4][cn]);
            }
            #pragma unroll
            for (int mt = 0; mt < 4; mt++)
                #pragma unroll
                for (int nt = 0; nt < 4; nt++)
                    mma_tf32(acc[mt][nt], a[mt], b[nt]);
        }
        __syncthreads();
    }

    #pragma unroll
    for (int mt = 0; mt < 4; mt++) {
        #pragma unroll
        for (int nt = 0; nt < 4; nt++) {
            int n = n0 + wn * 32 + nt * 8 + 2 * tg;
            float2 bv = *(const float2*)&bias[n];
            #pragma unroll
            for (int half = 0; half < 2; half++) {
                int m = m0 + wm * 64 + mt * 16 + g + half * 8;
                float v0 = acc[mt][nt][half * 2 + 0] + bv.x;
                float v1 = acc[mt][nt][half * 2 + 1] + bv.y;
                if (HEAD_SPLIT) {
                    int bi = m >> 11, s = m & (SS - 1);
                    int h = n >> 6, d = n & 63;
                    *(float2*)&Y[(((size_t)(bi * HH + h)) * SS + s) * DEPTH + d] =
                        make_float2(v0, v1);
                } else {
                    *(float2*)&Y[(size_t)m * DDIM + n] = make_float2(v0, v1);
                }
            }
        }
    }
}

// ---------------------------------------------------------------------------
// Scores: attn[bh,q,k] = (q128 tile · k128 tile^T)*0.125 + mask*(-1e9)
// Block 128q x 128k, K=64 fully resident. 8 warps (2m x 4n), warp 64x32.
// grid (BH, S/128, S/128) — x=bh so 16 heads share each mask tile in L2.
// ---------------------------------------------------------------------------
__global__ void __launch_bounds__(256) scores_tc(
    const float* __restrict__ mask, float* __restrict__ attn)
{
    extern __shared__ float dsm[];
    float (*Qs)[68] = (float(*)[68])dsm;               // [q][d]   128x68
    float (*Ks)[68] = (float(*)[68])(dsm + 128 * 68);  // [key][d] 128x68

    const int bh = blockIdx.x;
    const int k0 = blockIdx.y * 128;
    const int q0 = blockIdx.z * 128;
    const int b = bh >> 4;

    const float* qbase = g_q + (size_t)bh * SS * DEPTH;
    const float* kbase = g_k + (size_t)bh * SS * DEPTH;
    const int tid = threadIdx.x;
    const int w = tid >> 5, lane = tid & 31;
    const int wm = w >> 2, wn = w & 3;
    const int g = lane >> 2, tg = lane & 3;

    #pragma unroll
    for (int it = 0; it < 8; it++) {                   // 128x64 = 2048 float4
        int f = it * 256 + tid;
        int row = f >> 4, c4 = f & 15;
        float4 q = *(const float4*)&qbase[(size_t)(q0 + row) * DEPTH + c4 * 4];
        *(float4*)&Qs[row][c4 * 4] = cvt4(q);
        float4 k = *(const float4*)&kbase[(size_t)(k0 + row) * DEPTH + c4 * 4];
        *(float4*)&Ks[row][c4 * 4] = cvt4(k);
    }
    __syncthreads();

    float acc[4][4][4];
    #pragma unroll
    for (int mt = 0; mt < 4; mt++)
        #pragma unroll
        for (int nt = 0; nt < 4; nt++)
            #pragma unroll
            for (int r = 0; r < 4; r++) acc[mt][nt][r] = 0.f;

    #pragma unroll
    for (int ks = 0; ks < 8; ks++) {
        int kc = ks * 8;
        uint32_t a[4][4], bfr[4][2];
        #pragma unroll
        for (int mt = 0; mt < 4; mt++) {
            int rm = wm * 64 + mt * 16;
            a[mt][0] = fau(Qs[rm + g][kc + tg]);
            a[mt][1] = fau(Qs[rm + g + 8][kc + tg]);
            a[mt][2] = fau(Qs[rm + g][kc + tg + 4]);
            a[mt][3] = fau(Qs[rm + g + 8][kc + tg + 4]);
        }
        #pragma unroll
        for (int nt = 0; nt < 4; nt++) {
            int cn = wn * 32 + nt * 8 + g;
            bfr[nt][0] = fau(Ks[cn][kc + tg]);
            bfr[nt][1] = fau(Ks[cn][kc + tg + 4]);
        }
        #pragma unroll
        for (int mt = 0; mt < 4; mt++)
            #pragma unroll
            for (int nt = 0; nt < 4; nt++)
                mma_tf32(acc[mt][nt], a[mt], bfr[nt]);
    }

    const float scale = 0.125f;
    #pragma unroll
    for (int mt = 0; mt < 4; mt++) {
        #pragma unroll
        for (int nt = 0; nt < 4; nt++) {
            int kg = k0 + wn * 32 + nt * 8 + 2 * tg;
            #pragma unroll
            for (int half = 0; half < 2; half++) {
                int qg = q0 + wm * 64 + mt * 16 + g + half * 8;
                float2 mv = *(const float2*)&mask[((size_t)b * SS + qg) * SS + kg];
                float v0 = acc[mt][nt][half * 2 + 0] * scale + mv.x * (-1e9f);
                float v1 = acc[mt][nt][half * 2 + 1] * scale + mv.y * (-1e9f);
                *(float2*)&attn[(((size_t)bh) * SS + qg) * SS + kg] = make_float2(v0, v1);
            }
        }
    }
}

// ---------------------------------------------------------------------------
// Row softmax in place. One block per row, 8 elements/thread in registers.
// ---------------------------------------------------------------------------
__global__ void __launch_bounds__(256) softmax_kernel(float* __restrict__ attn)
{
    float* p = attn + (size_t)blockIdx.x * SS;
    const int tid = threadIdx.x;

    float v[8];
    float mx = -3.4e38f;
    #pragma unroll
    for (int i = 0; i < 8; i++) {
        v[i] = p[i * 256 + tid];
        mx = fmaxf(mx, v[i]);
    }
    #pragma unroll
    for (int o = 16; o > 0; o >>= 1)
        mx = fmaxf(mx, __shfl_xor_sync(0xffffffffu, mx, o));

    __shared__ float red[8];
    if ((tid & 31) == 0) red[tid >> 5] = mx;
    __syncthreads();
    float m = red[0];
    #pragma unroll
    for (int i = 1; i < 8; i++) m = fmaxf(m, red[i]);
    __syncthreads();

    float s = 0.f;
    #pragma unroll
    for (int i = 0; i < 8; i++) {
        v[i] = __expf(v[i] - m);
        s += v[i];
    }
    #pragma unroll
    for (int o = 16; o > 0; o >>= 1)
        s += __shfl_xor_sync(0xffffffffu, s, o);
    if ((tid & 31) == 0) red[tid >> 5] = s;
    __syncthreads();
    float tot = 0.f;
    #pragma unroll
    for (int i = 0; i < 8; i++) tot += red[i];

    float inv = 1.0f / tot;
    #pragma unroll
    for (int i = 0; i < 8; i++)
        p[i * 256 + tid] = v[i] * inv;
}

// ---------------------------------------------------------------------------
// AV: rep[b,h] = attn[b,h](2048x2048) @ v[b,h](2048x64) -> concat layout
// Block 128q x 64dv, ktile 64. 8 warps (2m x 4n), warp tile 64x16.
// ---------------------------------------------------------------------------
__global__ void __launch_bounds__(256) av_tc(const float* __restrict__ attn)
{
    extern __shared__ float dsm[];
    float (*As)[68] = (float(*)[68])dsm;               // [q][k]  128x68
    float (*Vs)[72] = (float(*)[72])(dsm + 128 * 68);  // [k][dv] 64x72 (k-major, ≡8 mod 32)

    const int bh = blockIdx.x;
    const int m0 = blockIdx.y * 128;
    const int b = bh >> 4, h = bh & 15;

    const float* abase = attn + (size_t)bh * SS * SS;
    const float* vbase = g_v + (size_t)bh * SS * DEPTH;
    const int tid = threadIdx.x;
    const int w = tid >> 5, lane = tid & 31;
    const int wm = w >> 2, wn = w & 3;
    const int g = lane >> 2, tg = lane & 3;

    float acc[4][2][4];
    #pragma unroll
    for (int mt = 0; mt < 4; mt++)
        #pragma unroll
        for (int nt = 0; nt < 2; nt++)
            #pragma unroll
            for (int r = 0; r < 4; r++) acc[mt][nt][r] = 0.f;

    for (int kt = 0; kt < SS; kt += 64) {
        #pragma unroll
        for (int it = 0; it < 8; it++) {               // attn 128x64 = 2048 float4
            int f = it * 256 + tid;
            int row = f >> 4, c4 = f & 15;
            float4 v = *(const float4*)&abase[(size_t)(m0 + row) * SS + kt + c4 * 4];
            *(float4*)&As[row][c4 * 4] = cvt4(v);
        }
        #pragma unroll
        for (int it = 0; it < 4; it++) {               // V 64x64 = 1024 float4
            int f = it * 256 + tid;
            int row = f >> 4, c4 = f & 15;
            float4 v = *(const float4*)&vbase[(size_t)(kt + row) * DEPTH + c4 * 4];
            *(float4*)&Vs[row][c4 * 4] = cvt4(v);
        }
        __syncthreads();

        #pragma unroll
        for (int ks = 0; ks < 8; ks++) {
            int kc = ks * 8;
            uint32_t a[4][4], bfr[2][2];
            #pragma unroll
            for (int mt = 0; mt < 4; mt++) {
                int rm = wm * 64 + mt * 16;
                a[mt][0] = fau(As[rm + g][kc + tg]);
                a[mt][1] = fau(As[rm + g + 8][kc + tg]);
                a[mt][2] = fau(As[rm + g][kc + tg + 4]);
                a[mt][3] = fau(As[rm + g + 8][kc + tg + 4]);
            }
            #pragma unroll
            for (int nt = 0; nt < 2; nt++) {
                int cn = wn * 16 + nt * 8 + g;
                bfr[nt][0] = fau(Vs[kc + tg][cn]);
                bfr[nt][1] = fau(Vs[kc + tg + 4][cn]);
            }
            #pragma unroll
            for (int mt = 0; mt < 4; mt++)
                #pragma unroll
                for (int nt = 0; nt < 2; nt++)
                    mma_tf32(acc[mt][nt], a[mt], bfr[nt]);
        }
        __syncthreads();
    }

    #pragma unroll
    for (int mt = 0; mt < 4; mt++) {
        #pragma unroll
        for (int nt = 0; nt < 2; nt++) {
            int dv = wn * 16 + nt * 8 + 2 * tg;
            #pragma unroll
            for (int half = 0; half < 2; half++) {
                int s = m0 + wm * 64 + mt * 16 + g + half * 8;
                *(float2*)&g_concat[((size_t)b * SS + s) * DDIM + h * DEPTH + dv] =
                    make_float2(acc[mt][nt][half * 2 + 0], acc[mt][nt][half * 2 + 1]);
            }
        }
    }
}

// ---------------------------------------------------------------------------
extern "C" void kernel_launch(void* const* d_in, const int* in_sizes, int n_in,
                              void* d_out, int out_size)
{
    const float* Q    = (const float*)d_in[0];
    const float* K    = (const float*)d_in[1];
    const float* V    = (const float*)d_in[2];
    const float* Mask = (const float*)d_in[3];
    const float* Wq   = (const float*)d_in[4];
    const float* bq   = (const float*)d_in[5];
    const float* Wk   = (const float*)d_in[6];
    const float* bk   = (const float*)d_in[7];
    const float* Wv   = (const float*)d_in[8];
    const float* bv   = (const float*)d_in[9];
    const float* Wo   = (const float*)d_in[10];
    const float* bo   = (const float*)d_in[11];

    float* out = (float*)d_out;

    const size_t out_elems  = (size_t)BB * SS * DDIM;       //   8,388,608
    const size_t attn_elems = (size_t)BB * HH * SS * SS;    // 268,435,456

    float *qp, *kp, *vp, *cp, *attn;
    cudaGetSymbolAddress((void**)&qp, g_q);
    cudaGetSymbolAddress((void**)&kp, g_k);
    cudaGetSymbolAddress((void**)&vp, g_v);
    cudaGetSymbolAddress((void**)&cp, g_concat);

    if ((size_t)out_size >= out_elems + attn_elems) {
        attn = out + out_elems;
    } else {
        cudaGetSymbolAddress((void**)&attn, g_attn_scratch);
    }

    const int scoresSmem = (128 * 68 + 128 * 68) * 4;   // 69632
    const int avSmem     = (128 * 68 + 64 * 72) * 4;    // 53248
    cudaFuncSetAttribute(scores_tc, cudaFuncAttributeMaxDynamicSharedMemorySize, scoresSmem);
    cudaFuncSetAttribute(av_tc,     cudaFuncAttributeMaxDynamicSharedMemorySize, avSmem);

    dim3 gGemm(DDIM / 128, MROWS / 128);   // (8, 64)
    gemm_tc<true><<<gGemm, 256>>>(Q, Wq, bq, qp);
    gemm_tc<true><<<gGemm, 256>>>(K, Wk, bk, kp);
    gemm_tc<true><<<gGemm, 256>>>(V, Wv, bv, vp);

    dim3 gScores(BH, SS / 128, SS / 128);  // (64, 16, 16)
    scores_tc<<<gScores, 256, scoresSmem>>>(Mask, attn);

    softmax_kernel<<<(unsigned)(BH * SS), 256>>>(attn);   // 131072 rows

    dim3 gAV(BH, SS / 128);                // (64, 16)
    av_tc<<<gAV, 256, avSmem>>>(attn);

    gemm_tc<false><<<gGemm, 256>>>(cp, Wo, bo, out);
}

// round 12
// speedup vs baseline: 2.0184x; 1.0231x over previous
#include <cuda_runtime.h>
#include <cstddef>
#include <cstdint>

#define BB 4
#define SS 2048
#define DDIM 1024
#define HH 16
#define DEPTH 64
#define MROWS (BB*SS)          // 8192
#define BH (BB*HH)             // 64
#define NROWS (BH*SS)          // 131072 attention rows
#define KCHUNKS 4              // scores k-chunks (each 512 keys)

// Scratch (allocation-free rule: __device__ globals)
__device__ float g_q[(size_t)BB*HH*SS*DEPTH];       // 32 MB
__device__ float g_k[(size_t)BB*HH*SS*DEPTH];
__device__ float g_v[(size_t)BB*HH*SS*DEPTH];
__device__ float g_concat[(size_t)BB*SS*DDIM];      // 32 MB
__device__ float g_rowpart[(size_t)KCHUNKS*NROWS];  // per (kchunk,row) exp-sums
__device__ float g_invsum[(size_t)NROWS];           // 1/rowsum
__device__ float g_attn_scratch[(size_t)BB*HH*SS*SS]; // 1.07 GB fallback

// ---------------------------------------------------------------------------
// tf32 helpers
// ---------------------------------------------------------------------------
__device__ __forceinline__ float to_tf32(float x) {
    float r; asm("cvt.rna.tf32.f32 %0, %1;" : "=f"(r) : "f"(x)); return r;
}
__device__ __forceinline__ float4 cvt4(float4 v) {
    float4 t;
    t.x = to_tf32(v.x); t.y = to_tf32(v.y);
    t.z = to_tf32(v.z); t.w = to_tf32(v.w);
    return t;
}
// D += A(16x8,row) * B(8x8,col) ; tf32 inputs, fp32 accum
__device__ __forceinline__ void mma_tf32(float* d, const uint32_t* a, const uint32_t* b) {
    asm volatile(
        "mma.sync.aligned.m16n8k8.row.col.f32.tf32.tf32.f32 "
        "{%0,%1,%2,%3}, {%4,%5,%6,%7}, {%8,%9}, {%0,%1,%2,%3};"
        : "+f"(d[0]), "+f"(d[1]), "+f"(d[2]), "+f"(d[3])
        : "r"(a[0]), "r"(a[1]), "r"(a[2]), "r"(a[3]), "r"(b[0]), "r"(b[1]));
}
__device__ __forceinline__ uint32_t fau(float x) { return __float_as_uint(x); }

// Fragment mapping: g = lane>>2, tg = lane&3
// A: a0=(g,tg) a1=(g+8,tg) a2=(g,tg+4) a3=(g+8,tg+4)
// B: b0=(k=tg,n=g) b1=(k=tg+4,n=g)
// D: c0=(g,2tg) c1=(g,2tg+1) c2=(g+8,2tg) c3=(g+8,2tg+1)
// Conflict-free smem: row-major stride ≡ 4 (mod 32); k-major stride ≡ 8 (mod 32)

// ---------------------------------------------------------------------------
// Projection/output GEMM: Y[8192,1024] = X @ W + bias
// ---------------------------------------------------------------------------
template<bool HEAD_SPLIT>
__global__ void __launch_bounds__(256) gemm_tc(
    const float* __restrict__ X, const float* __restrict__ W,
    const float* __restrict__ bias, float* __restrict__ Y)
{
    __shared__ float As[128][36];    // [m][k]
    __shared__ float Bs[32][136];    // [k][n]

    const int m0 = blockIdx.y * 128;
    const int n0 = blockIdx.x * 128;
    const int tid = threadIdx.x;
    const int w = tid >> 5, lane = tid & 31;
    const int wm = w >> 2, wn = w & 3;
    const int g = lane >> 2, tg = lane & 3;

    float acc[4][4][4];
    #pragma unroll
    for (int mt = 0; mt < 4; mt++)
        #pragma unroll
        for (int nt = 0; nt < 4; nt++)
            #pragma unroll
            for (int r = 0; r < 4; r++) acc[mt][nt][r] = 0.f;

    for (int kt = 0; kt < DDIM; kt += 32) {
        #pragma unroll
        for (int it = 0; it < 4; it++) {
            int f = it * 256 + tid;
            int row = f >> 3, c4 = f & 7;
            float4 v = *(const float4*)&X[(size_t)(m0 + row) * DDIM + kt + c4 * 4];
            *(float4*)&As[row][c4 * 4] = cvt4(v);
        }
        #pragma unroll
        for (int it = 0; it < 4; it++) {
            int f = it * 256 + tid;
            int row = f >> 5, c4 = f & 31;
            float4 v = *(const float4*)&W[(size_t)(kt + row) * DDIM + n0 + c4 * 4];
            *(float4*)&Bs[row][c4 * 4] = cvt4(v);
        }
        __syncthreads();

        #pragma unroll
        for (int ks = 0; ks < 4; ks++) {
            int kc = ks * 8;
            uint32_t a[4][4], b[4][2];
            #pragma unroll
            for (int mt = 0; mt < 4; mt++) {
                int rm = wm * 64 + mt * 16;
                a[mt][0] = fau(As[rm + g][kc + tg]);
                a[mt][1] = fau(As[rm + g + 8][kc + tg]);
                a[mt][2] = fau(As[rm + g][kc + tg + 4]);
                a[mt][3] = fau(As[rm + g + 8][kc + tg + 4]);
            }
            #pragma unroll
            for (int nt = 0; nt < 4; nt++) {
                int cn = wn * 32 + nt * 8 + g;
                b[nt][0] = fau(Bs[kc + tg][cn]);
                b[nt][1] = fau(Bs[kc + tg + 4][cn]);
            }
            #pragma unroll
            for (int mt = 0; mt < 4; mt++)
                #pragma unroll
                for (int nt = 0; nt < 4; nt++)
                    mma_tf32(acc[mt][nt], a[mt], b[nt]);
        }
        __syncthreads();
    }

    #pragma unroll
    for (int mt = 0; mt < 4; mt++) {
        #pragma unroll
        for (int nt = 0; nt < 4; nt++) {
            int n = n0 + wn * 32 + nt * 8 + 2 * tg;
            float2 bv = *(const float2*)&bias[n];
            #pragma unroll
            for (int half = 0; half < 2; half++) {
                int m = m0 + wm * 64 + mt * 16 + g + half * 8;
                float v0 = acc[mt][nt][half * 2 + 0] + bv.x;
                float v1 = acc[mt][nt][half * 2 + 1] + bv.y;
                if (HEAD_SPLIT) {
                    int bi = m >> 11, s = m & (SS - 1);
                    int h = n >> 6, d = n & 63;
                    *(float2*)&Y[(((size_t)(bi * HH + h)) * SS + s) * DEPTH + d] =
                        make_float2(v0, v1);
                } else {
                    *(float2*)&Y[(size_t)m * DDIM + n] = make_float2(v0, v1);
                }
            }
        }
    }
}

// ---------------------------------------------------------------------------
// Scores+exp: writes UNNORMALIZED exp(score) to attn, plus per-row partial
// sums (one slot per (kchunk,row) — deterministic, no atomics).
// Block: 128q x 512k (4 k-tiles with Q resident). 8 warps (2m x 4n).
// grid (BH, S/128 q, KCHUNKS).
// ---------------------------------------------------------------------------
__global__ void __launch_bounds__(256) scores_exp(
    const float* __restrict__ mask, float* __restrict__ attn)
{
    extern __shared__ float dsm[];
    float (*Qs)[68] = (float(*)[68])dsm;               // [q][d]   128x68
    float (*Ks)[68] = (float(*)[68])(dsm + 128 * 68);  // [key][d] 128x68
    float (*red)[128] = (float(*)[128])dsm;            // reused after k-loop

    const int bh = blockIdx.x;
    const int q0 = blockIdx.y * 128;
    const int kc = blockIdx.z;
    const int b = bh >> 4;

    const float* qbase = g_q + (size_t)bh * SS * DEPTH;
    const float* kbase = g_k + (size_t)bh * SS * DEPTH;
    const int tid = threadIdx.x;
    const int w = tid >> 5, lane = tid & 31;
    const int wm = w >> 2, wn = w & 3;
    const int g = lane >> 2, tg = lane & 3;

    // Q tile resident for all 4 k-tiles
    #pragma unroll
    for (int it = 0; it < 8; it++) {
        int f = it * 256 + tid;
        int row = f >> 4, c4 = f & 15;
        float4 q = *(const float4*)&qbase[(size_t)(q0 + row) * DEPTH + c4 * 4];
        *(float4*)&Qs[row][c4 * 4] = cvt4(q);
    }

    float rsum[4][2];           // per-thread row partials (rows: wm*64+mt*16+g+8*half)
    #pragma unroll
    for (int mt = 0; mt < 4; mt++) { rsum[mt][0] = 0.f; rsum[mt][1] = 0.f; }

    const float scale = 0.125f;

    for (int kt = 0; kt < 4; kt++) {
        const int k0 = kc * 512 + kt * 128;
        __syncthreads();        // prior MMA reads of Ks done / Qs fill visible
        #pragma unroll
        for (int it = 0; it < 8; it++) {
            int f = it * 256 + tid;
            int row = f >> 4, c4 = f & 15;
            float4 k = *(const float4*)&kbase[(size_t)(k0 + row) * DEPTH + c4 * 4];
            *(float4*)&Ks[row][c4 * 4] = cvt4(k);
        }
        __syncthreads();

        float acc[4][4][4];
        #pragma unroll
        for (int mt = 0; mt < 4; mt++)
            #pragma unroll
            for (int nt = 0; nt < 4; nt++)
                #pragma unroll
                for (int r = 0; r < 4; r++) acc[mt][nt][r] = 0.f;

        #pragma unroll
        for (int ks = 0; ks < 8; ks++) {
            int kcc = ks * 8;
            uint32_t a[4][4], bfr[4][2];
            #pragma unroll
            for (int mt = 0; mt < 4; mt++) {
                int rm = wm * 64 + mt * 16;
                a[mt][0] = fau(Qs[rm + g][kcc + tg]);
                a[mt][1] = fau(Qs[rm + g + 8][kcc + tg]);
                a[mt][2] = fau(Qs[rm + g][kcc + tg + 4]);
                a[mt][3] = fau(Qs[rm + g + 8][kcc + tg + 4]);
            }
            #pragma unroll
            for (int nt = 0; nt < 4; nt++) {
                int cn = wn * 32 + nt * 8 + g;
                bfr[nt][0] = fau(Ks[cn][kcc + tg]);
                bfr[nt][1] = fau(Ks[cn][kcc + tg + 4]);
            }
            #pragma unroll
            for (int mt = 0; mt < 4; mt++)
                #pragma unroll
                for (int nt = 0; nt < 4; nt++)
                    mma_tf32(acc[mt][nt], a[mt], bfr[nt]);
        }

        // Epilogue: e = exp(score); masked -> 0. Accumulate row partials.
        #pragma unroll
        for (int mt = 0; mt < 4; mt++) {
            #pragma unroll
            for (int nt = 0; nt < 4; nt++) {
                int kg = k0 + wn * 32 + nt * 8 + 2 * tg;
                #pragma unroll
                for (int half = 0; half < 2; half++) {
                    int qg = q0 + wm * 64 + mt * 16 + g + half * 8;
                    float2 mv = *(const float2*)&mask[((size_t)b * SS + qg) * SS + kg];
                    float e0 = (mv.x != 0.f) ? 0.f
                             : __expf(acc[mt][nt][half * 2 + 0] * scale);
                    float e1 = (mv.y != 0.f) ? 0.f
                             : __expf(acc[mt][nt][half * 2 + 1] * scale);
                    *(float2*)&attn[(((size_t)bh) * SS + qg) * SS + kg] =
                        make_float2(e0, e1);
                    rsum[mt][half] += e0 + e1;
                }
            }
        }
    }

    // Reduce partials: over tg (shfl), then over wn (smem, fixed order).
    #pragma unroll
    for (int mt = 0; mt < 4; mt++)
        #pragma unroll
        for (int half = 0; half < 2; half++) {
            float s = rsum[mt][half];
            s += __shfl_xor_sync(0xffffffffu, s, 1);
            s += __shfl_xor_sync(0xffffffffu, s, 2);
            rsum[mt][half] = s;
        }
    __syncthreads();           // done with Qs region; reuse as red[4][128]
    if (tg == 0) {
        #pragma unroll
        for (int mt = 0; mt < 4; mt++)
            #pragma unroll
            for (int half = 0; half < 2; half++)
                red[wn][wm * 64 + mt * 16 + g + half * 8] = rsum[mt][half];
    }
    __syncthreads();
    if (tid < 128) {
        float s = red[0][tid] + red[1][tid] + red[2][tid] + red[3][tid];
        g_rowpart[(size_t)kc * NROWS + (size_t)bh * SS + q0 + tid] = s;
    }
}

// ---------------------------------------------------------------------------
// invsum: per row, 1 / sum of KCHUNKS partials.
// ---------------------------------------------------------------------------
__global__ void __launch_bounds__(256) invsum_kernel()
{
    int r = blockIdx.x * 256 + threadIdx.x;
    float s = 0.f;
    #pragma unroll
    for (int c = 0; c < KCHUNKS; c++)
        s += g_rowpart[(size_t)c * NROWS + r];
    g_invsum[r] = 1.0f / s;
}

// ---------------------------------------------------------------------------
// AV + normalize: reads unnormalized exp, scales by invsum[row], writes the
// normalized attn back (final output) and MMAs it against V -> concat.
// Block 128q x 64dv, ktile 64. 8 warps (2m x 4n).
// ---------------------------------------------------------------------------
__global__ void __launch_bounds__(256) av_tc(float* __restrict__ attn)
{
    extern __shared__ float dsm[];
    float (*As)[68] = (float(*)[68])dsm;               // [q][k]  128x68
    float (*Vs)[72] = (float(*)[72])(dsm + 128 * 68);  // [k][dv] 64x72
    float* invs = dsm + 128 * 68 + 64 * 72;            // [128]

    const int bh = blockIdx.x;
    const int m0 = blockIdx.y * 128;
    const int b = bh >> 4, h = bh & 15;

    float* abase = attn + (size_t)bh * SS * SS;
    const float* vbase = g_v + (size_t)bh * SS * DEPTH;
    const int tid = threadIdx.x;
    const int w = tid >> 5, lane = tid & 31;
    const int wm = w >> 2, wn = w & 3;
    const int g = lane >> 2, tg = lane & 3;

    if (tid < 128)
        invs[tid] = g_invsum[(size_t)bh * SS + m0 + tid];
    __syncthreads();

    float acc[4][2][4];
    #pragma unroll
    for (int mt = 0; mt < 4; mt++)
        #pragma unroll
        for (int nt = 0; nt < 2; nt++)
            #pragma unroll
            for (int r = 0; r < 4; r++) acc[mt][nt][r] = 0.f;

    for (int kt = 0; kt < SS; kt += 64) {
        #pragma unroll
        for (int it = 0; it < 8; it++) {
            int f = it * 256 + tid;
            int row = f >> 4, c4 = f & 15;
            float4 v = *(const float4*)&abase[(size_t)(m0 + row) * SS + kt + c4 * 4];
            float iv = invs[row];
            v.x *= iv; v.y *= iv; v.z *= iv; v.w *= iv;
            *(float4*)&abase[(size_t)(m0 + row) * SS + kt + c4 * 4] = v;  // final attn
            *(float4*)&As[row][c4 * 4] = cvt4(v);
        }
        #pragma unroll
        for (int it = 0; it < 4; it++) {
            int f = it * 256 + tid;
            int row = f >> 4, c4 = f & 15;
            float4 v = *(const float4*)&vbase[(size_t)(kt + row) * DEPTH + c4 * 4];
            *(float4*)&Vs[row][c4 * 4] = cvt4(v);
        }
        __syncthreads();

        #pragma unroll
        for (int ks = 0; ks < 8; ks++) {
            int kc = ks * 8;
            uint32_t a[4][4], bfr[2][2];
            #pragma unroll
            for (int mt = 0; mt < 4; mt++) {
                int rm = wm * 64 + mt * 16;
                a[mt][0] = fau(As[rm + g][kc + tg]);
                a[mt][1] = fau(As[rm + g + 8][kc + tg]);
                a[mt][2] = fau(As[rm + g][kc + tg + 4]);
                a[mt][3] = fau(As[rm + g + 8][kc + tg + 4]);
            }
            #pragma unroll
            for (int nt = 0; nt < 2; nt++) {
                int cn = wn * 16 + nt * 8 + g;
                bfr[nt][0] = fau(Vs[kc + tg][cn]);
                bfr[nt][1] = fau(Vs[kc + tg + 4][cn]);
            }
            #pragma unroll
            for (int mt = 0; mt < 4; mt++)
                #pragma unroll
                for (int nt = 0; nt < 2; nt++)
                    mma_tf32(acc[mt][nt], a[mt], bfr[nt]);
        }
        __syncthreads();
    }

    #pragma unroll
    for (int mt = 0; mt < 4; mt++) {
        #pragma unroll
        for (int nt = 0; nt < 2; nt++) {
            int dv = wn * 16 + nt * 8 + 2 * tg;
            #pragma unroll
            for (int half = 0; half < 2; half++) {
                int s = m0 + wm * 64 + mt * 16 + g + half * 8;
                *(float2*)&g_concat[((size_t)b * SS + s) * DDIM + h * DEPTH + dv] =
                    make_float2(acc[mt][nt][half * 2 + 0], acc[mt][nt][half * 2 + 1]);
            }
        }
    }
}

// ---------------------------------------------------------------------------
extern "C" void kernel_launch(void* const* d_in, const int* in_sizes, int n_in,
                              void* d_out, int out_size)
{
    const float* Q    = (const float*)d_in[0];
    const float* K    = (const float*)d_in[1];
    const float* V    = (const float*)d_in[2];
    const float* Mask = (const float*)d_in[3];
    const float* Wq   = (const float*)d_in[4];
    const float* bq   = (const float*)d_in[5];
    const float* Wk   = (const float*)d_in[6];
    const float* bk   = (const float*)d_in[7];
    const float* Wv   = (const float*)d_in[8];
    const float* bv   = (const float*)d_in[9];
    const float* Wo   = (const float*)d_in[10];
    const float* bo   = (const float*)d_in[11];

    float* out = (float*)d_out;

    const size_t out_elems  = (size_t)BB * SS * DDIM;       //   8,388,608
    const size_t attn_elems = (size_t)BB * HH * SS * SS;    // 268,435,456

    float *qp, *kp, *vp, *cp, *attn;
    cudaGetSymbolAddress((void**)&qp, g_q);
    cudaGetSymbolAddress((void**)&kp, g_k);
    cudaGetSymbolAddress((void**)&vp, g_v);
    cudaGetSymbolAddress((void**)&cp, g_concat);

    if ((size_t)out_size >= out_elems + attn_elems) {
        attn = out + out_elems;
    } else {
        cudaGetSymbolAddress((void**)&attn, g_attn_scratch);
    }

    const int scoresSmem = (128 * 68 + 128 * 68) * 4;         // 69632
    const int avSmem     = (128 * 68 + 64 * 72 + 128) * 4;    // 53760
    cudaFuncSetAttribute(scores_exp, cudaFuncAttributeMaxDynamicSharedMemorySize, scoresSmem);
    cudaFuncSetAttribute(av_tc,      cudaFuncAttributeMaxDynamicSharedMemorySize, avSmem);

    dim3 gGemm(DDIM / 128, MROWS / 128);   // (8, 64)
    gemm_tc<true><<<gGemm, 256>>>(Q, Wq, bq, qp);
    gemm_tc<true><<<gGemm, 256>>>(K, Wk, bk, kp);
    gemm_tc<true><<<gGemm, 256>>>(V, Wv, bv, vp);

    dim3 gScores(BH, SS / 128, KCHUNKS);   // (64, 16, 4)
    scores_exp<<<gScores, 256, scoresSmem>>>(Mask, attn);

    invsum_kernel<<<NROWS / 256, 256>>>();

    dim3 gAV(BH, SS / 128);                // (64, 16)
    av_tc<<<gAV, 256, avSmem>>>(attn);

    gemm_tc<false><<<gGemm, 256>>>(cp, Wo, bo, out);
}

// round 14
// speedup vs baseline: 2.3757x; 1.1770x over previous
#include <cuda_runtime.h>
#include <cstddef>
#include <cstdint>

#define BB 4
#define SS 2048
#define DDIM 1024
#define HH 16
#define DEPTH 64
#define MROWS (BB*SS)          // 8192
#define BH (BB*HH)             // 64
#define NROWS (BH*SS)          // 131072 attention rows
#define KCHUNKS 4              // scores k-chunks (each 512 keys)

// Scratch (allocation-free rule: __device__ globals)
__device__ float g_q[(size_t)BB*HH*SS*DEPTH];       // 32 MB
__device__ float g_k[(size_t)BB*HH*SS*DEPTH];
__device__ float g_v[(size_t)BB*HH*SS*DEPTH];
__device__ float g_concat[(size_t)BB*SS*DDIM];      // 32 MB
__device__ float g_rowpart[(size_t)KCHUNKS*NROWS];  // per (kchunk,row) exp-sums
__device__ float g_invsum[(size_t)NROWS];           // 1/rowsum
__device__ float g_attn_scratch[(size_t)BB*HH*SS*SS]; // 1.07 GB fallback

// ---------------------------------------------------------------------------
// tf32 helpers
// ---------------------------------------------------------------------------
__device__ __forceinline__ float to_tf32(float x) {
    float r; asm("cvt.rna.tf32.f32 %0, %1;" : "=f"(r) : "f"(x)); return r;
}
__device__ __forceinline__ float4 cvt4(float4 v) {
    float4 t;
    t.x = to_tf32(v.x); t.y = to_tf32(v.y);
    t.z = to_tf32(v.z); t.w = to_tf32(v.w);
    return t;
}
// D += A(16x8,row) * B(8x8,col) ; tf32 inputs, fp32 accum
__device__ __forceinline__ void mma_tf32(float* d, const uint32_t* a, const uint32_t* b) {
    asm volatile(
        "mma.sync.aligned.m16n8k8.row.col.f32.tf32.tf32.f32 "
        "{%0,%1,%2,%3}, {%4,%5,%6,%7}, {%8,%9}, {%0,%1,%2,%3};"
        : "+f"(d[0]), "+f"(d[1]), "+f"(d[2]), "+f"(d[3])
        : "r"(a[0]), "r"(a[1]), "r"(a[2]), "r"(a[3]), "r"(b[0]), "r"(b[1]));
}
__device__ __forceinline__ uint32_t fau(float x) { return __float_as_uint(x); }

// Fragment mapping: g = lane>>2, tg = lane&3
// A: a0=(g,tg) a1=(g+8,tg) a2=(g,tg+4) a3=(g+8,tg+4)
// B: b0=(k=tg,n=g) b1=(k=tg+4,n=g)
// D: c0=(g,2tg) c1=(g,2tg+1) c2=(g+8,2tg) c3=(g+8,2tg+1)
// Conflict-free smem: row-major stride ≡ 4 (mod 32); k-major stride ≡ 8 (mod 32)

// ---------------------------------------------------------------------------
// Projection/output GEMM: Y[8192,1024] = X @ W + bias
// 2 CTAs/SM for latency hiding.
// ---------------------------------------------------------------------------
template<bool HEAD_SPLIT>
__global__ void __launch_bounds__(256, 2) gemm_tc(
    const float* __restrict__ X, const float* __restrict__ W,
    const float* __restrict__ bias, float* __restrict__ Y)
{
    __shared__ float As[128][36];    // [m][k]
    __shared__ float Bs[32][136];    // [k][n]

    const int m0 = blockIdx.y * 128;
    const int n0 = blockIdx.x * 128;
    const int tid = threadIdx.x;
    const int w = tid >> 5, lane = tid & 31;
    const int wm = w >> 2, wn = w & 3;
    const int g = lane >> 2, tg = lane & 3;

    float acc[4][4][4];
    #pragma unroll
    for (int mt = 0; mt < 4; mt++)
        #pragma unroll
        for (int nt = 0; nt < 4; nt++)
            #pragma unroll
            for (int r = 0; r < 4; r++) acc[mt][nt][r] = 0.f;

    for (int kt = 0; kt < DDIM; kt += 32) {
        #pragma unroll
        for (int it = 0; it < 4; it++) {
            int f = it * 256 + tid;
            int row = f >> 3, c4 = f & 7;
            float4 v = *(const float4*)&X[(size_t)(m0 + row) * DDIM + kt + c4 * 4];
            *(float4*)&As[row][c4 * 4] = cvt4(v);
        }
        #pragma unroll
        for (int it = 0; it < 4; it++) {
            int f = it * 256 + tid;
            int row = f >> 5, c4 = f & 31;
            float4 v = *(const float4*)&W[(size_t)(kt + row) * DDIM + n0 + c4 * 4];
            *(float4*)&Bs[row][c4 * 4] = cvt4(v);
        }
        __syncthreads();

        #pragma unroll
        for (int ks = 0; ks < 4; ks++) {
            int kc = ks * 8;
            uint32_t a[4][4];
            #pragma unroll
            for (int mt = 0; mt < 4; mt++) {
                int rm = wm * 64 + mt * 16;
                a[mt][0] = fau(As[rm + g][kc + tg]);
                a[mt][1] = fau(As[rm + g + 8][kc + tg]);
                a[mt][2] = fau(As[rm + g][kc + tg + 4]);
                a[mt][3] = fau(As[rm + g + 8][kc + tg + 4]);
            }
            #pragma unroll
            for (int nh = 0; nh < 2; nh++) {     // B frags in halves (reg pressure)
                uint32_t b[2][2];
                #pragma unroll
                for (int nt = 0; nt < 2; nt++) {
                    int cn = wn * 32 + (nh * 2 + nt) * 8 + g;
                    b[nt][0] = fau(Bs[kc + tg][cn]);
                    b[nt][1] = fau(Bs[kc + tg + 4][cn]);
                }
                #pragma unroll
                for (int mt = 0; mt < 4; mt++)
                    #pragma unroll
                    for (int nt = 0; nt < 2; nt++)
                        mma_tf32(acc[mt][nh * 2 + nt], a[mt], b[nt]);
            }
        }
        __syncthreads();
    }

    #pragma unroll
    for (int mt = 0; mt < 4; mt++) {
        #pragma unroll
        for (int nt = 0; nt < 4; nt++) {
            int n = n0 + wn * 32 + nt * 8 + 2 * tg;
            float2 bv = *(const float2*)&bias[n];
            #pragma unroll
            for (int half = 0; half < 2; half++) {
                int m = m0 + wm * 64 + mt * 16 + g + half * 8;
                float v0 = acc[mt][nt][half * 2 + 0] + bv.x;
                float v1 = acc[mt][nt][half * 2 + 1] + bv.y;
                if (HEAD_SPLIT) {
                    int bi = m >> 11, s = m & (SS - 1);
                    int h = n >> 6, d = n & 63;
                    *(float2*)&Y[(((size_t)(bi * HH + h)) * SS + s) * DEPTH + d] =
                        make_float2(v0, v1);
                } else {
                    *(float2*)&Y[(size_t)m * DDIM + n] = make_float2(v0, v1);
                }
            }
        }
    }
}

// ---------------------------------------------------------------------------
// Scores+exp: writes UNNORMALIZED exp(score) to attn, plus per-row partial
// sums (one slot per (kchunk,row) — deterministic, no atomics).
// Block: 128q x 512k (4 k-tiles with Q resident). 2 CTAs/SM.
// grid (BH, S/128 q, KCHUNKS).
// ---------------------------------------------------------------------------
__global__ void __launch_bounds__(256, 2) scores_exp(
    const float* __restrict__ mask, float* __restrict__ attn)
{
    extern __shared__ float dsm[];
    float (*Qs)[68] = (float(*)[68])dsm;               // [q][d]   128x68
    float (*Ks)[68] = (float(*)[68])(dsm + 128 * 68);  // [key][d] 128x68
    float (*red)[128] = (float(*)[128])dsm;            // reused after k-loop

    const int bh = blockIdx.x;
    const int q0 = blockIdx.y * 128;
    const int kc = blockIdx.z;
    const int b = bh >> 4;

    const float* qbase = g_q + (size_t)bh * SS * DEPTH;
    const float* kbase = g_k + (size_t)bh * SS * DEPTH;
    const int tid = threadIdx.x;
    const int w = tid >> 5, lane = tid & 31;
    const int wm = w >> 2, wn = w & 3;
    const int g = lane >> 2, tg = lane & 3;

    // Q tile resident for all 4 k-tiles
    #pragma unroll
    for (int it = 0; it < 8; it++) {
        int f = it * 256 + tid;
        int row = f >> 4, c4 = f & 15;
        float4 q = *(const float4*)&qbase[(size_t)(q0 + row) * DEPTH + c4 * 4];
        *(float4*)&Qs[row][c4 * 4] = cvt4(q);
    }

    float rsum[4][2];           // per-thread row partials
    #pragma unroll
    for (int mt = 0; mt < 4; mt++) { rsum[mt][0] = 0.f; rsum[mt][1] = 0.f; }

    const float scale = 0.125f;

    for (int kt = 0; kt < 4; kt++) {
        const int k0 = kc * 512 + kt * 128;
        __syncthreads();
        #pragma unroll
        for (int it = 0; it < 8; it++) {
            int f = it * 256 + tid;
            int row = f >> 4, c4 = f & 15;
            float4 k = *(const float4*)&kbase[(size_t)(k0 + row) * DEPTH + c4 * 4];
            *(float4*)&Ks[row][c4 * 4] = cvt4(k);
        }
        __syncthreads();

        float acc[4][4][4];
        #pragma unroll
        for (int mt = 0; mt < 4; mt++)
            #pragma unroll
            for (int nt = 0; nt < 4; nt++)
                #pragma unroll
                for (int r = 0; r < 4; r++) acc[mt][nt][r] = 0.f;

        #pragma unroll
        for (int ks = 0; ks < 8; ks++) {
            int kcc = ks * 8;
            uint32_t a[4][4];
            #pragma unroll
            for (int mt = 0; mt < 4; mt++) {
                int rm = wm * 64 + mt * 16;
                a[mt][0] = fau(Qs[rm + g][kcc + tg]);
                a[mt][1] = fau(Qs[rm + g + 8][kcc + tg]);
                a[mt][2] = fau(Qs[rm + g][kcc + tg + 4]);
                a[mt][3] = fau(Qs[rm + g + 8][kcc + tg + 4]);
            }
            #pragma unroll
            for (int nh = 0; nh < 2; nh++) {   // B frags in halves
                uint32_t bfr[2][2];
                #pragma unroll
                for (int nt = 0; nt < 2; nt++) {
                    int cn = wn * 32 + (nh * 2 + nt) * 8 + g;
                    bfr[nt][0] = fau(Ks[cn][kcc + tg]);
                    bfr[nt][1] = fau(Ks[cn][kcc + tg + 4]);
                }
                #pragma unroll
                for (int mt = 0; mt < 4; mt++)
                    #pragma unroll
                    for (int nt = 0; nt < 2; nt++)
                        mma_tf32(acc[mt][nh * 2 + nt], a[mt], bfr[nt]);
            }
        }

        // Epilogue: e = exp(score); masked -> 0. Accumulate row partials.
        #pragma unroll
        for (int mt = 0; mt < 4; mt++) {
            #pragma unroll
            for (int nt = 0; nt < 4; nt++) {
                int kg = k0 + wn * 32 + nt * 8 + 2 * tg;
                #pragma unroll
                for (int half = 0; half < 2; half++) {
                    int qg = q0 + wm * 64 + mt * 16 + g + half * 8;
                    float2 mv = *(const float2*)&mask[((size_t)b * SS + qg) * SS + kg];
                    float e0 = (mv.x != 0.f) ? 0.f
                             : __expf(acc[mt][nt][half * 2 + 0] * scale);
                    float e1 = (mv.y != 0.f) ? 0.f
                             : __expf(acc[mt][nt][half * 2 + 1] * scale);
                    *(float2*)&attn[(((size_t)bh) * SS + qg) * SS + kg] =
                        make_float2(e0, e1);
                    rsum[mt][half] += e0 + e1;
                }
            }
        }
    }

    // Reduce partials: over tg (shfl), then over wn (smem, fixed order).
    #pragma unroll
    for (int mt = 0; mt < 4; mt++)
        #pragma unroll
        for (int half = 0; half < 2; half++) {
            float s = rsum[mt][half];
            s += __shfl_xor_sync(0xffffffffu, s, 1);
            s += __shfl_xor_sync(0xffffffffu, s, 2);
            rsum[mt][half] = s;
        }
    __syncthreads();           // done with Qs region; reuse as red[4][128]
    if (tg == 0) {
        #pragma unroll
        for (int mt = 0; mt < 4; mt++)
            #pragma unroll
            for (int half = 0; half < 2; half++)
                red[wn][wm * 64 + mt * 16 + g + half * 8] = rsum[mt][half];
    }
    __syncthreads();
    if (tid < 128) {
        float s = red[0][tid] + red[1][tid] + red[2][tid] + red[3][tid];
        g_rowpart[(size_t)kc * NROWS + (size_t)bh * SS + q0 + tid] = s;
    }
}

// ---------------------------------------------------------------------------
// invsum: per row, 1 / sum of KCHUNKS partials.
// ---------------------------------------------------------------------------
__global__ void __launch_bounds__(256) invsum_kernel()
{
    int r = blockIdx.x * 256 + threadIdx.x;
    float s = 0.f;
    #pragma unroll
    for (int c = 0; c < KCHUNKS; c++)
        s += g_rowpart[(size_t)c * NROWS + r];
    g_invsum[r] = 1.0f / s;
}

// ---------------------------------------------------------------------------
// AV + normalize: reads unnormalized exp, scales by invsum[row], writes the
// normalized attn back (final output) and MMAs it against V -> concat.
// Block 128q x 64dv, ktile 64. 2 CTAs/SM.
// ---------------------------------------------------------------------------
__global__ void __launch_bounds__(256, 2) av_tc(float* __restrict__ attn)
{
    extern __shared__ float dsm[];
    float (*As)[68] = (float(*)[68])dsm;               // [q][k]  128x68
    float (*Vs)[72] = (float(*)[72])(dsm + 128 * 68);  // [k][dv] 64x72
    float* invs = dsm + 128 * 68 + 64 * 72;            // [128]

    const int bh = blockIdx.x;
    const int m0 = blockIdx.y * 128;
    const int b = bh >> 4, h = bh & 15;

    float* abase = attn + (size_t)bh * SS * SS;
    const float* vbase = g_v + (size_t)bh * SS * DEPTH;
    const int tid = threadIdx.x;
    const int w = tid >> 5, lane = tid & 31;
    const int wm = w >> 2, wn = w & 3;
    const int g = lane >> 2, tg = lane & 3;

    if (tid < 128)
        invs[tid] = g_invsum[(size_t)bh * SS + m0 + tid];
    __syncthreads();

    float acc[4][2][4];
    #pragma unroll
    for (int mt = 0; mt < 4; mt++)
        #pragma unroll
        for (int nt = 0; nt < 2; nt++)
            #pragma unroll
            for (int r = 0; r < 4; r++) acc[mt][nt][r] = 0.f;

    for (int kt = 0; kt < SS; kt += 64) {
        #pragma unroll
        for (int it = 0; it < 8; it++) {
            int f = it * 256 + tid;
            int row = f >> 4, c4 = f & 15;
            float4 v = *(const float4*)&abase[(size_t)(m0 + row) * SS + kt + c4 * 4];
            float iv = invs[row];
            v.x *= iv; v.y *= iv; v.z *= iv; v.w *= iv;
            *(float4*)&abase[(size_t)(m0 + row) * SS + kt + c4 * 4] = v;  // final attn
            *(float4*)&As[row][c4 * 4] = cvt4(v);
        }
        #pragma unroll
        for (int it = 0; it < 4; it++) {
            int f = it * 256 + tid;
            int row = f >> 4, c4 = f & 15;
            float4 v = *(const float4*)&vbase[(size_t)(kt + row) * DEPTH + c4 * 4];
            *(float4*)&Vs[row][c4 * 4] = cvt4(v);
        }
        __syncthreads();

        #pragma unroll
        for (int ks = 0; ks < 8; ks++) {
            int kc = ks * 8;
            uint32_t a[4][4], bfr[2][2];
            #pragma unroll
            for (int mt = 0; mt < 4; mt++) {
                int rm = wm * 64 + mt * 16;
                a[mt][0] = fau(As[rm + g][kc + tg]);
                a[mt][1] = fau(As[rm + g + 8][kc + tg]);
                a[mt][2] = fau(As[rm + g][kc + tg + 4]);
                a[mt][3] = fau(As[rm + g + 8][kc + tg + 4]);
            }
            #pragma unroll
            for (int nt = 0; nt < 2; nt++) {
                int cn = wn * 16 + nt * 8 + g;
                bfr[nt][0] = fau(Vs[kc + tg][cn]);
                bfr[nt][1] = fau(Vs[kc + tg + 4][cn]);
            }
            #pragma unroll
            for (int mt = 0; mt < 4; mt++)
                #pragma unroll
                for (int nt = 0; nt < 2; nt++)
                    mma_tf32(acc[mt][nt], a[mt], bfr[nt]);
        }
        __syncthreads();
    }

    #pragma unroll
    for (int mt = 0; mt < 4; mt++) {
        #pragma unroll
        for (int nt = 0; nt < 2; nt++) {
            int dv = wn * 16 + nt * 8 + 2 * tg;
            #pragma unroll
            for (int half = 0; half < 2; half++) {
                int s = m0 + wm * 64 + mt * 16 + g + half * 8;
                *(float2*)&g_concat[((size_t)b * SS + s) * DDIM + h * DEPTH + dv] =
                    make_float2(acc[mt][nt][half * 2 + 0], acc[mt][nt][half * 2 + 1]);
            }
        }
    }
}

// ---------------------------------------------------------------------------
extern "C" void kernel_launch(void* const* d_in, const int* in_sizes, int n_in,
                              void* d_out, int out_size)
{
    const float* Q    = (const float*)d_in[0];
    const float* K    = (const float*)d_in[1];
    const float* V    = (const float*)d_in[2];
    const float* Mask = (const float*)d_in[3];
    const float* Wq   = (const float*)d_in[4];
    const float* bq   = (const float*)d_in[5];
    const float* Wk   = (const float*)d_in[6];
    const float* bk   = (const float*)d_in[7];
    const float* Wv   = (const float*)d_in[8];
    const float* bv   = (const float*)d_in[9];
    const float* Wo   = (const float*)d_in[10];
    const float* bo   = (const float*)d_in[11];

    float* out = (float*)d_out;

    const size_t out_elems  = (size_t)BB * SS * DDIM;       //   8,388,608
    const size_t attn_elems = (size_t)BB * HH * SS * SS;    // 268,435,456

    float *qp, *kp, *vp, *cp, *attn;
    cudaGetSymbolAddress((void**)&qp, g_q);
    cudaGetSymbolAddress((void**)&kp, g_k);
    cudaGetSymbolAddress((void**)&vp, g_v);
    cudaGetSymbolAddress((void**)&cp, g_concat);

    if ((size_t)out_size >= out_elems + attn_elems) {
        attn = out + out_elems;
    } else {
        cudaGetSymbolAddress((void**)&attn, g_attn_scratch);
    }

    const int scoresSmem = (128 * 68 + 128 * 68) * 4;         // 69632
    const int avSmem     = (128 * 68 + 64 * 72 + 128) * 4;    // 53760
    cudaFuncSetAttribute(scores_exp, cudaFuncAttributeMaxDynamicSharedMemorySize, scoresSmem);
    cudaFuncSetAttribute(av_tc,      cudaFuncAttributeMaxDynamicSharedMemorySize, avSmem);

    dim3 gGemm(DDIM / 128, MROWS / 128);   // (8, 64)
    gemm_tc<true><<<gGemm, 256>>>(Q, Wq, bq, qp);
    gemm_tc<true><<<gGemm, 256>>>(K, Wk, bk, kp);
    gemm_tc<true><<<gGemm, 256>>>(V, Wv, bv, vp);

    dim3 gScores(BH, SS / 128, KCHUNKS);   // (64, 16, 4)
    scores_exp<<<gScores, 256, scoresSmem>>>(Mask, attn);

    invsum_kernel<<<NROWS / 256, 256>>>();

    dim3 gAV(BH, SS / 128);                // (64, 16)
    av_tc<<<gAV, 256, avSmem>>>(attn);

    gemm_tc<false><<<gGemm, 256>>>(cp, Wo, bo, out);
}

// round 17
// speedup vs baseline: 2.9115x; 1.2256x over previous
#include <cuda_runtime.h>
#include <cstddef>
#include <cstdint>

#define BB 4
#define SS 2048
#define DDIM 1024
#define HH 16
#define DEPTH 64
#define MROWS (BB*SS)          // 8192
#define BH (BB*HH)             // 64
#define NROWS (BH*SS)          // 131072 attention rows
#define KCHUNKS 4              // scores k-chunks (each 512 keys)

// Scratch (allocation-free rule: __device__ globals)
__device__ float g_q[(size_t)BB*HH*SS*DEPTH];       // 32 MB (tf32-rounded)
__device__ float g_k[(size_t)BB*HH*SS*DEPTH];
__device__ float g_v[(size_t)BB*HH*SS*DEPTH];
__device__ float g_concat[(size_t)BB*SS*DDIM];      // 32 MB
__device__ float g_rowpart[(size_t)KCHUNKS*NROWS];  // per (kchunk,row) exp-sums
__device__ float g_invsum[(size_t)NROWS];           // 1/rowsum
__device__ float g_attn_scratch[(size_t)BB*HH*SS*SS]; // 1.07 GB fallback

// ---------------------------------------------------------------------------
// helpers
// ---------------------------------------------------------------------------
__device__ __forceinline__ float to_tf32(float x) {
    float r; asm("cvt.rna.tf32.f32 %0, %1;" : "=f"(r) : "f"(x)); return r;
}
__device__ __forceinline__ float4 cvt4(float4 v) {
    float4 t;
    t.x = to_tf32(v.x); t.y = to_tf32(v.y);
    t.z = to_tf32(v.z); t.w = to_tf32(v.w);
    return t;
}
__device__ __forceinline__ void mma_tf32(float* d, const uint32_t* a, const uint32_t* b) {
    asm volatile(
        "mma.sync.aligned.m16n8k8.row.col.f32.tf32.tf32.f32 "
        "{%0,%1,%2,%3}, {%4,%5,%6,%7}, {%8,%9}, {%0,%1,%2,%3};"
        : "+f"(d[0]), "+f"(d[1]), "+f"(d[2]), "+f"(d[3])
        : "r"(a[0]), "r"(a[1]), "r"(a[2]), "r"(a[3]), "r"(b[0]), "r"(b[1]));
}
__device__ __forceinline__ uint32_t fau(float x) { return __float_as_uint(x); }

__device__ __forceinline__ void cp16(float* smem_dst, const float* gsrc) {
    uint32_t d = (uint32_t)__cvta_generic_to_shared(smem_dst);
    asm volatile("cp.async.ca.shared.global [%0], [%1], 16;" :: "r"(d), "l"(gsrc));
}
__device__ __forceinline__ void cp_commit() {
    asm volatile("cp.async.commit_group;");
}
template<int N> __device__ __forceinline__ void cp_wait() {
    asm volatile("cp.async.wait_group %0;" :: "n"(N));
}

// Fragment mapping: g = lane>>2, tg = lane&3
// A: a0=(g,tg) a1=(g+8,tg) a2=(g,tg+4) a3=(g+8,tg+4)
// B: b0=(k=tg,n=g) b1=(k=tg+4,n=g)
// D: c0=(g,2tg) c1=(g,2tg+1) c2=(g+8,2tg) c3=(g+8,2tg+1)
// Conflict-free smem: row-major stride ≡ 4 (mod 32); k-major stride ≡ 8 (mod 32)

// ---------------------------------------------------------------------------
// Projection/output GEMM: Y[8192,1024] = X @ W + bias. 2 CTAs/SM.
// HEAD_SPLIT path rounds outputs to tf32 (consumed by tensor-core kernels).
// ---------------------------------------------------------------------------
template<bool HEAD_SPLIT>
__global__ void __launch_bounds__(256, 2) gemm_tc(
    const float* __restrict__ X, const float* __restrict__ W,
    const float* __restrict__ bias, float* __restrict__ Y)
{
    __shared__ float As[128][36];    // [m][k]
    __shared__ float Bs[32][136];    // [k][n]

    const int m0 = blockIdx.y * 128;
    const int n0 = blockIdx.x * 128;
    const int tid = threadIdx.x;
    const int w = tid >> 5, lane = tid & 31;
    const int wm = w >> 2, wn = w & 3;
    const int g = lane >> 2, tg = lane & 3;

    float acc[4][4][4];
    #pragma unroll
    for (int mt = 0; mt < 4; mt++)
        #pragma unroll
        for (int nt = 0; nt < 4; nt++)
            #pragma unroll
            for (int r = 0; r < 4; r++) acc[mt][nt][r] = 0.f;

    for (int kt = 0; kt < DDIM; kt += 32) {
        #pragma unroll
        for (int it = 0; it < 4; it++) {
            int f = it * 256 + tid;
            int row = f >> 3, c4 = f & 7;
            float4 v = *(const float4*)&X[(size_t)(m0 + row) * DDIM + kt + c4 * 4];
            *(float4*)&As[row][c4 * 4] = cvt4(v);
        }
        #pragma unroll
        for (int it = 0; it < 4; it++) {
            int f = it * 256 + tid;
            int row = f >> 5, c4 = f & 31;
            float4 v = *(const float4*)&W[(size_t)(kt + row) * DDIM + n0 + c4 * 4];
            *(float4*)&Bs[row][c4 * 4] = cvt4(v);
        }
        __syncthreads();

        #pragma unroll
        for (int ks = 0; ks < 4; ks++) {
            int kc = ks * 8;
            uint32_t a[4][4];
            #pragma unroll
            for (int mt = 0; mt < 4; mt++) {
                int rm = wm * 64 + mt * 16;
                a[mt][0] = fau(As[rm + g][kc + tg]);
                a[mt][1] = fau(As[rm + g + 8][kc + tg]);
                a[mt][2] = fau(As[rm + g][kc + tg + 4]);
                a[mt][3] = fau(As[rm + g + 8][kc + tg + 4]);
            }
            #pragma unroll
            for (int nh = 0; nh < 2; nh++) {
                uint32_t b[2][2];
                #pragma unroll
                for (int nt = 0; nt < 2; nt++) {
                    int cn = wn * 32 + (nh * 2 + nt) * 8 + g;
                    b[nt][0] = fau(Bs[kc + tg][cn]);
                    b[nt][1] = fau(Bs[kc + tg + 4][cn]);
                }
                #pragma unroll
                for (int mt = 0; mt < 4; mt++)
                    #pragma unroll
                    for (int nt = 0; nt < 2; nt++)
                        mma_tf32(acc[mt][nh * 2 + nt], a[mt], b[nt]);
            }
        }
        __syncthreads();
    }

    #pragma unroll
    for (int mt = 0; mt < 4; mt++) {
        #pragma unroll
        for (int nt = 0; nt < 4; nt++) {
            int n = n0 + wn * 32 + nt * 8 + 2 * tg;
            float2 bv = *(const float2*)&bias[n];
            #pragma unroll
            for (int half = 0; half < 2; half++) {
                int m = m0 + wm * 64 + mt * 16 + g + half * 8;
                float v0 = acc[mt][nt][half * 2 + 0] + bv.x;
                float v1 = acc[mt][nt][half * 2 + 1] + bv.y;
                if (HEAD_SPLIT) {
                    v0 = to_tf32(v0); v1 = to_tf32(v1);
                    int bi = m >> 11, s = m & (SS - 1);
                    int h = n >> 6, d = n & 63;
                    *(float2*)&Y[(((size_t)(bi * HH + h)) * SS + s) * DEPTH + d] =
                        make_float2(v0, v1);
                } else {
                    *(float2*)&Y[(size_t)m * DDIM + n] = make_float2(v0, v1);
                }
            }
        }
    }
}

// ---------------------------------------------------------------------------
// Scores+exp: writes UNNORMALIZED tf32-rounded exp(score) to attn + per-row
// partial sums. Block 128q x 512k, cp.async double-buffered K tiles.
// grid (BH, S/128 q, KCHUNKS). 2 CTAs/SM.
// ---------------------------------------------------------------------------
__global__ void __launch_bounds__(256, 2) scores_exp(
    const float* __restrict__ mask, float* __restrict__ attn)
{
    extern __shared__ float dsm[];
    float (*Qs)[68] = (float(*)[68])dsm;                       // 128x68
    // two K buffers, each 128x68
    float (*red)[128] = (float(*)[128])dsm;                    // reused at end

    const int bh = blockIdx.x;
    const int q0 = blockIdx.y * 128;
    const int kc = blockIdx.z;
    const int b = bh >> 4;

    const float* qbase = g_q + (size_t)bh * SS * DEPTH;
    const float* kbase = g_k + (size_t)bh * SS * DEPTH;
    const int tid = threadIdx.x;
    const int w = tid >> 5, lane = tid & 31;
    const int wm = w >> 2, wn = w & 3;
    const int g = lane >> 2, tg = lane & 3;

    // Q fill + K tile 0 prefetch (one commit group)
    #pragma unroll
    for (int it = 0; it < 8; it++) {
        int f = it * 256 + tid;
        int row = f >> 4, c4 = f & 15;
        cp16(&Qs[row][c4 * 4], &qbase[(size_t)(q0 + row) * DEPTH + c4 * 4]);
    }
    {
        const int k0 = kc * 512;
        float (*K0)[68] = (float(*)[68])(dsm + 128 * 68);
        #pragma unroll
        for (int it = 0; it < 8; it++) {
            int f = it * 256 + tid;
            int row = f >> 4, c4 = f & 15;
            cp16(&K0[row][c4 * 4], &kbase[(size_t)(k0 + row) * DEPTH + c4 * 4]);
        }
    }
    cp_commit();

    float rsum[4][2];
    #pragma unroll
    for (int mt = 0; mt < 4; mt++) { rsum[mt][0] = 0.f; rsum[mt][1] = 0.f; }

    const float scale = 0.125f;

    for (int kt = 0; kt < 4; kt++) {
        if (kt < 3) {                       // prefetch next K tile
            const int k0n = kc * 512 + (kt + 1) * 128;
            float (*Kn)[68] = (float(*)[68])(dsm + 128 * 68 + ((kt + 1) & 1) * 128 * 68);
            #pragma unroll
            for (int it = 0; it < 8; it++) {
                int f = it * 256 + tid;
                int row = f >> 4, c4 = f & 15;
                cp16(&Kn[row][c4 * 4], &kbase[(size_t)(k0n + row) * DEPTH + c4 * 4]);
            }
            cp_commit();
            cp_wait<1>();
        } else {
            cp_wait<0>();
        }
        __syncthreads();

        float (*Ks)[68] = (float(*)[68])(dsm + 128 * 68 + (kt & 1) * 128 * 68);
        const int k0 = kc * 512 + kt * 128;

        float acc[4][4][4];
        #pragma unroll
        for (int mt = 0; mt < 4; mt++)
            #pragma unroll
            for (int nt = 0; nt < 4; nt++)
                #pragma unroll
                for (int r = 0; r < 4; r++) acc[mt][nt][r] = 0.f;

        #pragma unroll
        for (int ks = 0; ks < 8; ks++) {
            int kcc = ks * 8;
            uint32_t a[4][4];
            #pragma unroll
            for (int mt = 0; mt < 4; mt++) {
                int rm = wm * 64 + mt * 16;
                a[mt][0] = fau(Qs[rm + g][kcc + tg]);
                a[mt][1] = fau(Qs[rm + g + 8][kcc + tg]);
                a[mt][2] = fau(Qs[rm + g][kcc + tg + 4]);
                a[mt][3] = fau(Qs[rm + g + 8][kcc + tg + 4]);
            }
            #pragma unroll
            for (int nh = 0; nh < 2; nh++) {
                uint32_t bfr[2][2];
                #pragma unroll
                for (int nt = 0; nt < 2; nt++) {
                    int cn = wn * 32 + (nh * 2 + nt) * 8 + g;
                    bfr[nt][0] = fau(Ks[cn][kcc + tg]);
                    bfr[nt][1] = fau(Ks[cn][kcc + tg + 4]);
                }
                #pragma unroll
                for (int mt = 0; mt < 4; mt++)
                    #pragma unroll
                    for (int nt = 0; nt < 2; nt++)
                        mma_tf32(acc[mt][nh * 2 + nt], a[mt], bfr[nt]);
            }
        }

        // Epilogue: e = tf32(exp(score)); masked -> 0.
        #pragma unroll
        for (int mt = 0; mt < 4; mt++) {
            #pragma unroll
            for (int nt = 0; nt < 4; nt++) {
                int kg = k0 + wn * 32 + nt * 8 + 2 * tg;
                #pragma unroll
                for (int half = 0; half < 2; half++) {
                    int qg = q0 + wm * 64 + mt * 16 + g + half * 8;
                    float2 mv = *(const float2*)&mask[((size_t)b * SS + qg) * SS + kg];
                    float e0 = (mv.x != 0.f) ? 0.f
                             : to_tf32(__expf(acc[mt][nt][half * 2 + 0] * scale));
                    float e1 = (mv.y != 0.f) ? 0.f
                             : to_tf32(__expf(acc[mt][nt][half * 2 + 1] * scale));
                    *(float2*)&attn[(((size_t)bh) * SS + qg) * SS + kg] =
                        make_float2(e0, e1);
                    rsum[mt][half] += e0 + e1;
                }
            }
        }
        __syncthreads();
    }

    // Reduce partials: over tg (shfl), then over wn (smem, fixed order).
    #pragma unroll
    for (int mt = 0; mt < 4; mt++)
        #pragma unroll
        for (int half = 0; half < 2; half++) {
            float s = rsum[mt][half];
            s += __shfl_xor_sync(0xffffffffu, s, 1);
            s += __shfl_xor_sync(0xffffffffu, s, 2);
            rsum[mt][half] = s;
        }
    if (tg == 0) {
        #pragma unroll
        for (int mt = 0; mt < 4; mt++)
            #pragma unroll
            for (int half = 0; half < 2; half++)
                red[wn][wm * 64 + mt * 16 + g + half * 8] = rsum[mt][half];
    }
    __syncthreads();
    if (tid < 128) {
        float s = red[0][tid] + red[1][tid] + red[2][tid] + red[3][tid];
        g_rowpart[(size_t)kc * NROWS + (size_t)bh * SS + q0 + tid] = s;
    }
}

// ---------------------------------------------------------------------------
// invsum: per row, 1 / sum of KCHUNKS partials.
// ---------------------------------------------------------------------------
__global__ void __launch_bounds__(256) invsum_kernel()
{
    int r = blockIdx.x * 256 + threadIdx.x;
    float s = 0.f;
    #pragma unroll
    for (int c = 0; c < KCHUNKS; c++)
        s += g_rowpart[(size_t)c * NROWS + r];
    g_invsum[r] = 1.0f / s;
}

// ---------------------------------------------------------------------------
// AV: cp.async double-buffered. MMA on raw (tf32) exp values; row-normalize
// the ACCUMULATOR at the end (exact: rep = inv*(e@V)). Normalized attn is
// written float4-coalesced from smem. Block 128q x 64dv, ktile 64. 2 CTAs/SM.
// ---------------------------------------------------------------------------
__global__ void __launch_bounds__(256, 2) av_tc(float* __restrict__ attn)
{
    extern __shared__ float dsm[];
    // As[2]: 128x68 each; Vs[2]: 64x72 each; invs: 128
    float* invs = dsm + 2 * 128 * 68 + 2 * 64 * 72;

    const int bh = blockIdx.x;
    const int m0 = blockIdx.y * 128;
    const int b = bh >> 4, h = bh & 15;

    float* abase = attn + (size_t)bh * SS * SS;
    const float* vbase = g_v + (size_t)bh * SS * DEPTH;
    const int tid = threadIdx.x;
    const int w = tid >> 5, lane = tid & 31;
    const int wm = w >> 2, wn = w & 3;
    const int g = lane >> 2, tg = lane & 3;

    if (tid < 128)
        invs[tid] = g_invsum[(size_t)bh * SS + m0 + tid];

    // prefetch tile 0
    {
        float (*A0)[68] = (float(*)[68])dsm;
        float (*V0)[72] = (float(*)[72])(dsm + 2 * 128 * 68);
        #pragma unroll
        for (int it = 0; it < 8; it++) {
            int f = it * 256 + tid;
            int row = f >> 4, c4 = f & 15;
            cp16(&A0[row][c4 * 4], &abase[(size_t)(m0 + row) * SS + c4 * 4]);
        }
        #pragma unroll
        for (int it = 0; it < 4; it++) {
            int f = it * 256 + tid;
            int row = f >> 4, c4 = f & 15;
            cp16(&V0[row][c4 * 4], &vbase[(size_t)row * DEPTH + c4 * 4]);
        }
        cp_commit();
    }

    float acc[4][2][4];
    #pragma unroll
    for (int mt = 0; mt < 4; mt++)
        #pragma unroll
        for (int nt = 0; nt < 2; nt++)
            #pragma unroll
            for (int r = 0; r < 4; r++) acc[mt][nt][r] = 0.f;

    for (int t = 0; t < 32; t++) {
        const int kt = t * 64;
        if (t < 31) {                     // prefetch next tile
            const int ktn = kt + 64;
            float (*An)[68] = (float(*)[68])(dsm + ((t + 1) & 1) * 128 * 68);
            float (*Vn)[72] = (float(*)[72])(dsm + 2 * 128 * 68 + ((t + 1) & 1) * 64 * 72);
            #pragma unroll
            for (int it = 0; it < 8; it++) {
                int f = it * 256 + tid;
                int row = f >> 4, c4 = f & 15;
                cp16(&An[row][c4 * 4], &abase[(size_t)(m0 + row) * SS + ktn + c4 * 4]);
            }
            #pragma unroll
            for (int it = 0; it < 4; it++) {
                int f = it * 256 + tid;
                int row = f >> 4, c4 = f & 15;
                cp16(&Vn[row][c4 * 4], &vbase[(size_t)(ktn + row) * DEPTH + c4 * 4]);
            }
            cp_commit();
            cp_wait<1>();
        } else {
            cp_wait<0>();
        }
        __syncthreads();

        float (*As)[68] = (float(*)[68])(dsm + (t & 1) * 128 * 68);
        float (*Vs)[72] = (float(*)[72])(dsm + 2 * 128 * 68 + (t & 1) * 64 * 72);

        // Write normalized attn (final output), float4 coalesced.
        #pragma unroll
        for (int it = 0; it < 8; it++) {
            int f = it * 256 + tid;
            int row = f >> 4, c4 = f & 15;
            float4 v = *(const float4*)&As[row][c4 * 4];
            float iv = invs[row];
            v.x *= iv; v.y *= iv; v.z *= iv; v.w *= iv;
            *(float4*)&abase[(size_t)(m0 + row) * SS + kt + c4 * 4] = v;
        }

        #pragma unroll
        for (int ks = 0; ks < 8; ks++) {
            int kc = ks * 8;
            uint32_t a[4][4], bfr[2][2];
            #pragma unroll
            for (int mt = 0; mt < 4; mt++) {
                int rm = wm * 64 + mt * 16;
                a[mt][0] = fau(As[rm + g][kc + tg]);
                a[mt][1] = fau(As[rm + g + 8][kc + tg]);
                a[mt][2] = fau(As[rm + g][kc + tg + 4]);
                a[mt][3] = fau(As[rm + g + 8][kc + tg + 4]);
            }
            #pragma unroll
            for (int nt = 0; nt < 2; nt++) {
                int cn = wn * 16 + nt * 8 + g;
                bfr[nt][0] = fau(Vs[kc + tg][cn]);
                bfr[nt][1] = fau(Vs[kc + tg + 4][cn]);
            }
            #pragma unroll
            for (int mt = 0; mt < 4; mt++)
                #pragma unroll
                for (int nt = 0; nt < 2; nt++)
                    mma_tf32(acc[mt][nt], a[mt], bfr[nt]);
        }
        __syncthreads();
    }

    #pragma unroll
    for (int mt = 0; mt < 4; mt++) {
        #pragma unroll
        for (int half = 0; half < 2; half++) {
            int r = wm * 64 + mt * 16 + g + half * 8;
            float iv = invs[r];
            int s = m0 + r;
            #pragma unroll
            for (int nt = 0; nt < 2; nt++) {
                int dv = wn * 16 + nt * 8 + 2 * tg;
                *(float2*)&g_concat[((size_t)b * SS + s) * DDIM + h * DEPTH + dv] =
                    make_float2(acc[mt][nt][half * 2 + 0] * iv,
                                acc[mt][nt][half * 2 + 1] * iv);
            }
        }
    }
}

// ---------------------------------------------------------------------------
extern "C" void kernel_launch(void* const* d_in, const int* in_sizes, int n_in,
                              void* d_out, int out_size)
{
    const float* Q    = (const float*)d_in[0];
    const float* K    = (const float*)d_in[1];
    const float* V    = (const float*)d_in[2];
    const float* Mask = (const float*)d_in[3];
    const float* Wq   = (const float*)d_in[4];
    const float* bq   = (const float*)d_in[5];
    const float* Wk   = (const float*)d_in[6];
    const float* bk   = (const float*)d_in[7];
    const float* Wv   = (const float*)d_in[8];
    const float* bv   = (const float*)d_in[9];
    const float* Wo   = (const float*)d_in[10];
    const float* bo   = (const float*)d_in[11];

    float* out = (float*)d_out;

    const size_t out_elems  = (size_t)BB * SS * DDIM;       //   8,388,608
    const size_t attn_elems = (size_t)BB * HH * SS * SS;    // 268,435,456

    float *qp, *kp, *vp, *cp, *attn;
    cudaGetSymbolAddress((void**)&qp, g_q);
    cudaGetSymbolAddress((void**)&kp, g_k);
    cudaGetSymbolAddress((void**)&vp, g_v);
    cudaGetSymbolAddress((void**)&cp, g_concat);

    if ((size_t)out_size >= out_elems + attn_elems) {
        attn = out + out_elems;
    } else {
        cudaGetSymbolAddress((void**)&attn, g_attn_scratch);
    }

    const int scoresSmem = (3 * 128 * 68) * 4;                      // 104448
    const int avSmem     = (2 * 128 * 68 + 2 * 64 * 72 + 128) * 4;  // 107008
    cudaFuncSetAttribute(scores_exp, cudaFuncAttributeMaxDynamicSharedMemorySize, scoresSmem);
    cudaFuncSetAttribute(av_tc,      cudaFuncAttributeMaxDynamicSharedMemorySize, avSmem);

    dim3 gGemm(DDIM / 128, MROWS / 128);   // (8, 64)
    gemm_tc<true><<<gGemm, 256>>>(Q, Wq, bq, qp);
    gemm_tc<true><<<gGemm, 256>>>(K, Wk, bk, kp);
    gemm_tc<true><<<gGemm, 256>>>(V, Wv, bv, vp);

    dim3 gScores(BH, SS / 128, KCHUNKS);   // (64, 16, 4)
    scores_exp<<<gScores, 256, scoresSmem>>>(Mask, attn);

    invsum_kernel<<<NROWS / 256, 256>>>();

    dim3 gAV(BH, SS / 128);                // (64, 16)
    av_tc<<<gAV, 256, avSmem>>>(attn);

    gemm_tc<false><<<gGemm, 256>>>(cp, Wo, bo, out);
}